// round 8
// baseline (speedup 1.0000x reference)
#include <cuda_runtime.h>
#include <cuda_bf16.h>
#include <math.h>
#include <stdint.h>

#define NN 50000
#define EE 800000
#define TT 12
#define D  128

typedef unsigned short u16;
typedef unsigned int   u32;

// ---------------- scratch ----------------
__device__ float g_norm_src[NN], g_norm_dst[NN];
__device__ int g_ocnt[NN], g_cnt[NN + 1], g_rowptr[NN + 1], g_cursor[NN];
__device__ int g_srcsorted[EE];
__device__ __align__(16) u16 g_xhi[(size_t)NN * TT * D];   // h pre-split (pair-packed along k)
__device__ __align__(16) u16 g_xlo[(size_t)NN * TT * D];
__device__ __align__(16) u16 g_mhi[(size_t)NN * D];        // spmm out
__device__ __align__(16) u16 g_mlo[(size_t)NN * D];
__device__ __align__(16) float g_xact[(size_t)NN * D];     // layer-1 act (fp32, spmm2 input)
__device__ __align__(16) u16 g_hhi0[(size_t)NN * D], g_hlo0[(size_t)NN * D];
__device__ __align__(16) u16 g_hhi1[(size_t)NN * D], g_hlo1[(size_t)NN * D];
__device__ __align__(16) float g_c[(size_t)NN * D];
__device__ __align__(16) u16 g_wlhi[512 * 256], g_wllo[512 * 256];  // [n][k], quad-permuted rows
__device__ __align__(16) u16 g_w1hi[128 * 128], g_w1lo[128 * 128];  // [n][k]
__device__ __align__(16) u16 g_w2hi[128 * 128], g_w2lo[128 * 128];
__device__ float g_biasp[512];
__device__ float g_hs[TT * D];

// ---------------- helpers ----------------
__device__ __forceinline__ float gelu_exact(float v) {
    return 0.5f * v * (1.0f + erff(v * 0.70710678118654752f));
}
__device__ __forceinline__ float sigmoidf_(float v) {
    return 1.0f / (1.0f + __expf(-v));
}
__device__ __forceinline__ void bsplit(float x, u16& h, u16& l) {
    __nv_bfloat16 bh = __float2bfloat16(x);
    float hr = __bfloat162float(bh);
    __nv_bfloat16 bl = __float2bfloat16(x - hr);
    h = *(u16*)&bh;
    l = *(u16*)&bl;
}
__device__ __forceinline__ void mma16(float (&c)[4], uint4 a, u32 b0, u32 b1) {
    asm volatile(
        "mma.sync.aligned.m16n8k16.row.col.f32.bf16.bf16.f32 "
        "{%0,%1,%2,%3},{%4,%5,%6,%7},{%8,%9},{%0,%1,%2,%3};\n"
        : "+f"(c[0]), "+f"(c[1]), "+f"(c[2]), "+f"(c[3])
        : "r"(a.x), "r"(a.y), "r"(a.z), "r"(a.w), "r"(b0), "r"(b1));
}

// ---------------- setup kernels ----------------
__global__ void init_kernel(float* __restrict__ out_ht) {
    int i = blockIdx.x * blockDim.x + threadIdx.x;
    if (i < NN * D) {
        g_c[i] = 0.0f;
        g_hhi0[i] = 0; g_hlo0[i] = 0;
        out_ht[i] = 0.0f;
    }
    if (i < NN) { g_ocnt[i] = 0; g_cnt[i] = 0; }
    if (i == 0) g_cnt[NN] = 0;
    if (i < TT * D) g_hs[i] = 0.0f;
}
__global__ void hist_kernel(const int* __restrict__ src, const int* __restrict__ dst) {
    int e = blockIdx.x * blockDim.x + threadIdx.x;
    if (e < EE) {
        atomicAdd(&g_ocnt[src[e]], 1);
        atomicAdd(&g_cnt[dst[e]], 1);
    }
}
__global__ void norm_kernel() {
    int i = blockIdx.x * blockDim.x + threadIdx.x;
    if (i < NN) {
        g_norm_src[i] = rsqrtf(fmaxf((float)g_ocnt[i], 1.0f));
        g_norm_dst[i] = rsqrtf(fmaxf((float)g_cnt[i], 1.0f));
    }
}
__global__ void scan_kernel() {
    __shared__ int ps[1024];
    const int CH = (NN + 1023) / 1024;
    int t = threadIdx.x;
    int beg = t * CH, end = min(beg + CH, NN);
    int s = 0;
    for (int i = beg; i < end; i++) s += g_cnt[i];
    ps[t] = s;
    __syncthreads();
    if (t == 0) {
        int a = 0;
        for (int i = 0; i < 1024; i++) { int v = ps[i]; ps[i] = a; a += v; }
    }
    __syncthreads();
    int off = ps[t];
    for (int i = beg; i < end; i++) {
        g_rowptr[i] = off;
        g_cursor[i] = off;
        off += g_cnt[i];
    }
    if (t == 1023) g_rowptr[NN] = off;
}
__global__ void scatter_kernel(const int* __restrict__ src, const int* __restrict__ dst) {
    int e = blockIdx.x * blockDim.x + threadIdx.x;
    if (e < EE) {
        int d = dst[e];
        int p = atomicAdd(&g_cursor[d], 1);
        g_srcsorted[p] = src[e];
    }
}
__global__ void convh_kernel(const float* __restrict__ h) {
    size_t q = (size_t)blockIdx.x * blockDim.x + threadIdx.x;
    if (q >= (size_t)NN * TT * D / 4) return;
    float4 v = ((const float4*)h)[q];
    u16 h0, h1, h2, h3, l0, l1, l2, l3;
    bsplit(v.x, h0, l0); bsplit(v.y, h1, l1);
    bsplit(v.z, h2, l2); bsplit(v.w, h3, l3);
    ((uint2*)g_xhi)[q] = make_uint2((u32)h0 | ((u32)h1 << 16), (u32)h2 | ((u32)h3 << 16));
    ((uint2*)g_xlo)[q] = make_uint2((u32)l0 | ((u32)l1 << 16), (u32)l2 | ((u32)l3 << 16));
}
// LSTM weights: row_out j*4+g <- row_in g*128+j, cols [w_ih|w_hh]
__global__ void wlprep_kernel(const float* __restrict__ w_ih, const float* __restrict__ w_hh,
                              const float* __restrict__ b_ih, const float* __restrict__ b_hh) {
    int idx = blockIdx.x * blockDim.x + threadIdx.x;
    if (idx >= 512 * 256) return;
    int ro = idx >> 8, k = idx & 255;
    int ri = (ro & 3) * D + (ro >> 2);
    float v = (k < D) ? w_ih[ri * D + k] : w_hh[ri * D + (k - D)];
    u16 hh, ll;
    bsplit(v, hh, ll);
    g_wlhi[idx] = hh; g_wllo[idx] = ll;
    if (k == 0) g_biasp[ro] = b_ih[ri] + b_hh[ri];
}
// graph weights: B[n][k] = W[k][n]
__global__ void wgprep_kernel(const float* __restrict__ Wg1, const float* __restrict__ Wg2) {
    int idx = blockIdx.x * blockDim.x + threadIdx.x;
    if (idx >= 2 * 128 * 128) return;
    int sel = idx >> 14, e = idx & 16383;
    int n = e >> 7, k = e & 127;
    float v = sel ? Wg2[k * 128 + n] : Wg1[k * 128 + n];
    u16 hh, ll;
    bsplit(v, hh, ll);
    if (sel) { g_w2hi[e] = hh; g_w2lo[e] = ll; }
    else     { g_w1hi[e] = hh; g_w1lo[e] = ll; }
}

// ---------------- SpMM: emits bf16 hi/lo pairs ----------------
__global__ __launch_bounds__(256) void spmm_kernel(const float* __restrict__ X, int ldx) {
    int w = (blockIdx.x * blockDim.x + threadIdx.x) >> 5;
    int lane = threadIdx.x & 31;
    if (w >= NN) return;
    int s0 = g_rowptr[w], s1 = g_rowptr[w + 1];
    float4 acc = make_float4(0.f, 0.f, 0.f, 0.f);
    for (int base = s0; base < s1; base += 32) {
        int n = min(32, s1 - base);
        int s = 0; float ns = 0.f;
        if (lane < n) {
            s = g_srcsorted[base + lane];
            ns = g_norm_src[s];
        }
        for (int j = 0; j < n; j++) {
            int   sj = __shfl_sync(0xffffffffu, s, j);
            float nj = __shfl_sync(0xffffffffu, ns, j);
            float4 v = *(const float4*)(X + (size_t)sj * ldx + lane * 4);
            acc.x += v.x * nj; acc.y += v.y * nj;
            acc.z += v.z * nj; acc.w += v.w * nj;
        }
    }
    float nd = g_norm_dst[w];
    u16 h0, h1, h2, h3, l0, l1, l2, l3;
    bsplit(acc.x * nd, h0, l0); bsplit(acc.y * nd, h1, l1);
    bsplit(acc.z * nd, h2, l2); bsplit(acc.w * nd, h3, l3);
    size_t q = ((size_t)w * D + lane * 4) >> 2;
    ((uint2*)g_mhi)[q] = make_uint2((u32)h0 | ((u32)h1 << 16), (u32)h2 | ((u32)h3 << 16));
    ((uint2*)g_mlo)[q] = make_uint2((u32)l0 | ((u32)l1 << 16), (u32)l2 | ((u32)l3 << 16));
}

// ==================================================================================
// bf16 3-term split GEMM, mma.m16n8k16, BM=128 BN=128 BK=16, double-buffered SMEM.
// 256 threads: 8 warps (2x4), warp tile 64x32.
// MODE 0: graph conv, K=128: C = gelu(A@B^T + bias); opt C store, opt hs colsum.
// MODE 1: LSTM, K=256 (A = [x_t | h]): fused cell epilogue. grid.y = 4.
// ==================================================================================
template <int MODE>
__global__ __launch_bounds__(256) void gemm_bf16(
    const u32* __restrict__ A0h, const u32* __restrict__ A0l, int ldap,   // pairs/row
    const u32* __restrict__ A1h, const u32* __restrict__ A1l,             // MODE1 h (ld 64)
    const u32* __restrict__ Bh,  const u32* __restrict__ Bl,  int ldbp,
    const float* __restrict__ bias,
    float* __restrict__ C, float* __restrict__ hsacc,
    u16* __restrict__ hoh, u16* __restrict__ hol,
    float* __restrict__ hta)
{
    __shared__ __align__(16) u32 sh[8192];   // 2 buffers x (Ahi 1024 | Alo 1024 | Bhi 1024 | Blo 1024)
    float* gtile = (float*)sh;               // epilogue [64][128]

    const int tid = threadIdx.x, lane = tid & 31;
    const int warpId = tid >> 5;
    const int warpM = warpId >> 2, warpN = warpId & 3;
    const int rowBase = blockIdx.x * 128;
    const int colBase = blockIdx.y * 128;
    const int r_ = tid >> 1, halfk = (tid & 1) * 4;

    float acc[4][4][4];
#pragma unroll
    for (int a = 0; a < 4; a++)
#pragma unroll
        for (int b = 0; b < 4; b++)
#pragma unroll
            for (int c = 0; c < 4; c++) acc[a][b][c] = 0.f;

    const int NCH = MODE ? 16 : 8;

    auto prefetch = [&](int ch, uint4& avh, uint4& avl, uint4& bvh, uint4& bvl) {
        const u32 *ah_, *al_;
        int po, ld;
        if (MODE == 1 && ch >= 8) { ah_ = A1h; al_ = A1l; po = (ch - 8) * 8 + halfk; ld = 64; }
        else                      { ah_ = A0h; al_ = A0l; po = ch * 8 + halfk; ld = ldap; }
        avh = make_uint4(0, 0, 0, 0); avl = avh;
        if (rowBase + r_ < NN) {
            avh = *(const uint4*)(ah_ + (size_t)(rowBase + r_) * ld + po);
            avl = *(const uint4*)(al_ + (size_t)(rowBase + r_) * ld + po);
        }
        int gc = (MODE ? colBase : 0) + r_;
        int pb = ch * 8 + halfk;
        bvh = *(const uint4*)(Bh + (size_t)gc * ldbp + pb);
        bvl = *(const uint4*)(Bl + (size_t)gc * ldbp + pb);
    };

    uint4 avh, avl, bvh, bvl;
    prefetch(0, avh, avl, bvh, bvl);

    for (int ch = 0; ch < NCH; ch++) {
        u32* base = sh + (ch & 1) * 4096;
        // ---- scatter prefetched regs into SMEM fragments ----
        {
            u32 ph[4] = {avh.x, avh.y, avh.z, avh.w};
            u32 pl[4] = {avl.x, avl.y, avl.z, avl.w};
            int m = r_ >> 4, row16 = r_ & 15;
#pragma unroll
            for (int j = 0; j < 4; j++) {
                int kp = halfk + j;
                int l = (row16 & 7) * 4 + (kp & 3);
                int rg = (row16 >> 3) | ((kp >> 2) << 1);
                int ad = (m * 32 + l) * 4 + rg;
                base[ad] = ph[j];
                base[1024 + ad] = pl[j];
            }
            u32 qh[4] = {bvh.x, bvh.y, bvh.z, bvh.w};
            u32 ql[4] = {bvl.x, bvl.y, bvl.z, bvl.w};
            int n = r_ >> 3;
#pragma unroll
            for (int j = 0; j < 4; j++) {
                int kp = halfk + j;
                int l = (r_ & 7) * 4 + (kp & 3);
                int rg = kp >> 2;
                int ad = (n * 32 + l) * 2 + rg;
                base[2048 + ad] = qh[j];
                base[3072 + ad] = ql[j];
            }
        }
        __syncthreads();
        if (ch + 1 < NCH) prefetch(ch + 1, avh, avl, bvh, bvl);
        // ---- compute ----
        const u32* As_hi = base;
        const u32* As_lo = base + 1024;
        const u32* Bs_hi = base + 2048;
        const u32* Bs_lo = base + 3072;
        uint4 ah[4], al[4];
#pragma unroll
        for (int mi = 0; mi < 4; mi++) {
            int fid = warpM * 4 + mi;
            ah[mi] = ((const uint4*)As_hi)[fid * 32 + lane];
            al[mi] = ((const uint4*)As_lo)[fid * 32 + lane];
        }
#pragma unroll
        for (int ni = 0; ni < 4; ni++) {
            int fid = warpN * 4 + ni;
            uint2 bh = ((const uint2*)Bs_hi)[fid * 32 + lane];
            uint2 bl = ((const uint2*)Bs_lo)[fid * 32 + lane];
#pragma unroll
            for (int mi = 0; mi < 4; mi++) {
                mma16(acc[mi][ni], ah[mi], bh.x, bh.y);
                mma16(acc[mi][ni], ah[mi], bl.x, bl.y);
                mma16(acc[mi][ni], al[mi], bh.x, bh.y);
            }
        }
        __syncthreads();
    }

    // ---- epilogue: stage through shared, 2 row-halves of 64 ----
    float csum[4] = {0.f, 0.f, 0.f, 0.f};
    const int cq = tid & 31;

    for (int half = 0; half < 2; half++) {
        __syncthreads();
        if (warpM == half) {
#pragma unroll
            for (int mi = 0; mi < 4; mi++) {
#pragma unroll
                for (int ni = 0; ni < 4; ni++) {
                    int rloc = mi * 16 + (lane >> 2);
                    int cloc = warpN * 32 + ni * 8 + (lane & 3) * 2;
                    float b0v = bias[colBase + cloc];
                    float b1v = bias[colBase + cloc + 1];
                    gtile[rloc * 128 + cloc]           = acc[mi][ni][0] + b0v;
                    gtile[rloc * 128 + cloc + 1]       = acc[mi][ni][1] + b1v;
                    gtile[(rloc + 8) * 128 + cloc]     = acc[mi][ni][2] + b0v;
                    gtile[(rloc + 8) * 128 + cloc + 1] = acc[mi][ni][3] + b1v;
                }
            }
        }
        __syncthreads();
#pragma unroll
        for (int i = 0; i < 8; i++) {
            int e = tid + i * 256;
            int rloc = e >> 5;
            int row = rowBase + half * 64 + rloc;
            if (MODE == 0) {
                float4 gv = *(const float4*)&gtile[rloc * 128 + cq * 4];
                float4 ov;
                ov.x = gelu_exact(gv.x);
                ov.y = gelu_exact(gv.y);
                ov.z = gelu_exact(gv.z);
                ov.w = gelu_exact(gv.w);
                if (row < NN) {
                    if (C != nullptr)
                        *(float4*)(C + (size_t)row * D + cq * 4) = ov;
                    csum[0] += ov.x; csum[1] += ov.y; csum[2] += ov.z; csum[3] += ov.w;
                }
            } else {
                if (row < NN) {
                    float4 gv = *(const float4*)&gtile[rloc * 128 + cq * 4];
                    int fg = blockIdx.y * 32 + cq;
                    size_t idx = (size_t)row * D + fg;
                    float cp = g_c[idx];
                    float cn = sigmoidf_(gv.y) * cp + sigmoidf_(gv.x) * tanhf(gv.z);
                    float ho = sigmoidf_(gv.w) * tanhf(cn);
                    g_c[idx] = cn;
                    hta[idx] += ho;
                    u16 hh, hl;
                    bsplit(ho, hh, hl);
                    hoh[idx] = hh;
                    hol[idx] = hl;
                }
            }
        }
    }
    if (MODE == 0 && hsacc != nullptr) {
#pragma unroll
        for (int j = 0; j < 4; j++) atomicAdd(&hsacc[cq * 4 + j], csum[j]);
    }
}

__global__ void finalize_kernel(float* __restrict__ out) {
    int idx = blockIdx.x * blockDim.x + threadIdx.x;
    if (idx < TT * D) out[idx] = g_hs[idx] * (1.0f / (float)NN);
    if (idx < NN * D) out[TT * D + idx] *= (1.0f / (float)TT);
}

// ---------------- launch ----------------
extern "C" void kernel_launch(void* const* d_in, const int* in_sizes, int n_in,
                              void* d_out, int out_size) {
    const float* h    = (const float*)d_in[0];
    const int*   src  = (const int*)d_in[1];
    const int*   dst  = (const int*)d_in[2];
    const float* Wg1  = (const float*)d_in[3];
    const float* bg1  = (const float*)d_in[4];
    const float* Wg2  = (const float*)d_in[5];
    const float* bg2  = (const float*)d_in[6];
    const float* w_ih = (const float*)d_in[7];
    const float* w_hh = (const float*)d_in[8];
    const float* b_ih = (const float*)d_in[9];
    const float* b_hh = (const float*)d_in[10];

    float* out    = (float*)d_out;
    float* out_ht = out + TT * D;

    u16 *pxhi, *pxlo, *pmhi, *pmlo, *ph0h, *ph0l, *ph1h, *ph1l;
    u16 *pwlh, *pwll, *pw1h, *pw1l, *pw2h, *pw2l;
    float *pxact, *pbp, *phs;
    cudaGetSymbolAddress((void**)&pxhi, g_xhi);
    cudaGetSymbolAddress((void**)&pxlo, g_xlo);
    cudaGetSymbolAddress((void**)&pmhi, g_mhi);
    cudaGetSymbolAddress((void**)&pmlo, g_mlo);
    cudaGetSymbolAddress((void**)&ph0h, g_hhi0);
    cudaGetSymbolAddress((void**)&ph0l, g_hlo0);
    cudaGetSymbolAddress((void**)&ph1h, g_hhi1);
    cudaGetSymbolAddress((void**)&ph1l, g_hlo1);
    cudaGetSymbolAddress((void**)&pwlh, g_wlhi);
    cudaGetSymbolAddress((void**)&pwll, g_wllo);
    cudaGetSymbolAddress((void**)&pw1h, g_w1hi);
    cudaGetSymbolAddress((void**)&pw1l, g_w1lo);
    cudaGetSymbolAddress((void**)&pw2h, g_w2hi);
    cudaGetSymbolAddress((void**)&pw2l, g_w2lo);
    cudaGetSymbolAddress((void**)&pxact, g_xact);
    cudaGetSymbolAddress((void**)&pbp, g_biasp);
    cudaGetSymbolAddress((void**)&phs, g_hs);

    // fork/join resources (host objects only; leaked deliberately — graph replays
    // do not re-invoke kernel_launch, and destroy during capture is unsafe)
    cudaStream_t s2;
    cudaStreamCreateWithFlags(&s2, cudaStreamNonBlocking);
    cudaEvent_t e1, e2;
    cudaEventCreateWithFlags(&e1, cudaEventDisableTiming);
    cudaEventCreateWithFlags(&e2, cudaEventDisableTiming);

    // common setup on main stream
    init_kernel<<<(NN * D + 255) / 256, 256>>>(out_ht);
    wlprep_kernel<<<(512 * 256 + 255) / 256, 256>>>(w_ih, w_hh, b_ih, b_hh);
    convh_kernel<<<(int)(((size_t)NN * TT * D / 4 + 255) / 256), 256>>>(h);

    // fork: LSTM chain on s2 (depends only on init/wlprep/convh)
    cudaEventRecord(e1, 0);
    cudaStreamWaitEvent(s2, e1, 0);

    const int gx = (NN + 127) / 128;   // 391
    u16 *hih = ph0h, *hil = ph0l, *hoh = ph1h, *hol = ph1l;
    for (int t = 0; t < TT; t++) {
        gemm_bf16<1><<<dim3(gx, 4), 256, 0, s2>>>(
            (u32*)pxhi + (size_t)t * 64, (u32*)pxlo + (size_t)t * 64, TT * 64,
            (u32*)hih, (u32*)hil,
            (u32*)pwlh, (u32*)pwll, 128, pbp,
            nullptr, nullptr, hoh, hol, out_ht);
        u16* t1 = hih; hih = hoh; hoh = t1;
        u16* t2 = hil; hil = hol; hol = t2;
    }
    cudaEventRecord(e2, s2);

    // graph chain on main stream
    hist_kernel<<<(EE + 255) / 256, 256>>>(src, dst);
    norm_kernel<<<(NN + 255) / 256, 256>>>();
    wgprep_kernel<<<(2 * 128 * 128 + 255) / 256, 256>>>(Wg1, Wg2);
    scan_kernel<<<1, 1024>>>();
    scatter_kernel<<<(EE + 255) / 256, 256>>>(src, dst);

    int spmm_blocks = (NN * 32 + 255) / 256;
    for (int t = 0; t < TT; t++) {
        spmm_kernel<<<spmm_blocks, 256>>>(h + t * D, TT * D);
        gemm_bf16<0><<<dim3(gx, 1), 256>>>((u32*)pmhi, (u32*)pmlo, 64, nullptr, nullptr,
                                           (u32*)pw1h, (u32*)pw1l, 64, bg1,
                                           pxact, nullptr, nullptr, nullptr, nullptr);
        spmm_kernel<<<spmm_blocks, 256>>>(pxact, D);
        gemm_bf16<0><<<dim3(gx, 1), 256>>>((u32*)pmhi, (u32*)pmlo, 64, nullptr, nullptr,
                                           (u32*)pw2h, (u32*)pw2l, 64, bg2,
                                           nullptr, phs + t * D, nullptr, nullptr, nullptr);
    }

    // join and finalize
    cudaStreamWaitEvent(0, e2, 0);
    finalize_kernel<<<(NN * D + 255) / 256, 256>>>(out);
}

// round 9
// speedup vs baseline: 1.2333x; 1.2333x over previous
#include <cuda_runtime.h>
#include <cuda_bf16.h>
#include <math.h>
#include <stdint.h>

#define NN 50000
#define EE 800000
#define TT 12
#define D  128

typedef unsigned short u16;
typedef unsigned int   u32;

// ---------------- scratch ----------------
__device__ float g_norm_src[NN], g_norm_dst[NN];
__device__ int g_ocnt[NN], g_cnt[NN + 1], g_rowptr[NN + 1], g_cursor[NN];
__device__ int g_srcsorted[EE];
__device__ __align__(16) u16 g_xhi[(size_t)NN * TT * D];   // h pre-split (pair-packed along k)
__device__ __align__(16) u16 g_xlo[(size_t)NN * TT * D];
__device__ __align__(16) u16 g_mhi[(size_t)NN * D];        // spmm out
__device__ __align__(16) u16 g_mlo[(size_t)NN * D];
__device__ __align__(16) float g_xact[(size_t)NN * D];     // layer-1 act (fp32, spmm2 input)
__device__ __align__(16) u16 g_hhi0[(size_t)NN * D], g_hlo0[(size_t)NN * D];
__device__ __align__(16) u16 g_hhi1[(size_t)NN * D], g_hlo1[(size_t)NN * D];
__device__ __align__(16) float g_c[(size_t)NN * D];
__device__ __align__(16) u16 g_wlhi[512 * 256], g_wllo[512 * 256];  // [n][k], quad-permuted rows
__device__ __align__(16) u16 g_w1hi[128 * 128], g_w1lo[128 * 128];  // [n][k]
__device__ __align__(16) u16 g_w2hi[128 * 128], g_w2lo[128 * 128];
__device__ float g_biasp[512];
__device__ float g_hs[TT * D];

// ---------------- helpers ----------------
__device__ __forceinline__ float gelu_exact(float v) {
    return 0.5f * v * (1.0f + erff(v * 0.70710678118654752f));
}
__device__ __forceinline__ float sigmoidf_(float v) {
    return 1.0f / (1.0f + __expf(-v));
}
__device__ __forceinline__ void bsplit(float x, u16& h, u16& l) {
    __nv_bfloat16 bh = __float2bfloat16(x);
    float hr = __bfloat162float(bh);
    __nv_bfloat16 bl = __float2bfloat16(x - hr);
    h = *(u16*)&bh;
    l = *(u16*)&bl;
}
__device__ __forceinline__ void mma16(float (&c)[4], uint4 a, u32 b0, u32 b1) {
    asm volatile(
        "mma.sync.aligned.m16n8k16.row.col.f32.bf16.bf16.f32 "
        "{%0,%1,%2,%3},{%4,%5,%6,%7},{%8,%9},{%0,%1,%2,%3};\n"
        : "+f"(c[0]), "+f"(c[1]), "+f"(c[2]), "+f"(c[3])
        : "r"(a.x), "r"(a.y), "r"(a.z), "r"(a.w), "r"(b0), "r"(b1));
}

// ---------------- setup kernels ----------------
__global__ void init_kernel(float* __restrict__ out_ht) {
    int i = blockIdx.x * blockDim.x + threadIdx.x;
    if (i < NN * D) {
        g_c[i] = 0.0f;
        g_hhi0[i] = 0; g_hlo0[i] = 0;
        out_ht[i] = 0.0f;
    }
    if (i < NN) { g_ocnt[i] = 0; g_cnt[i] = 0; }
    if (i == 0) g_cnt[NN] = 0;
    if (i < TT * D) g_hs[i] = 0.0f;
}
__global__ void hist_kernel(const int* __restrict__ src, const int* __restrict__ dst) {
    int e = blockIdx.x * blockDim.x + threadIdx.x;
    if (e < EE) {
        atomicAdd(&g_ocnt[src[e]], 1);
        atomicAdd(&g_cnt[dst[e]], 1);
    }
}
__global__ void norm_kernel() {
    int i = blockIdx.x * blockDim.x + threadIdx.x;
    if (i < NN) {
        g_norm_src[i] = rsqrtf(fmaxf((float)g_ocnt[i], 1.0f));
        g_norm_dst[i] = rsqrtf(fmaxf((float)g_cnt[i], 1.0f));
    }
}
__global__ void scan_kernel() {
    __shared__ int ps[1024];
    const int CH = (NN + 1023) / 1024;
    int t = threadIdx.x;
    int beg = t * CH, end = min(beg + CH, NN);
    int s = 0;
    for (int i = beg; i < end; i++) s += g_cnt[i];
    ps[t] = s;
    __syncthreads();
    if (t == 0) {
        int a = 0;
        for (int i = 0; i < 1024; i++) { int v = ps[i]; ps[i] = a; a += v; }
    }
    __syncthreads();
    int off = ps[t];
    for (int i = beg; i < end; i++) {
        g_rowptr[i] = off;
        g_cursor[i] = off;
        off += g_cnt[i];
    }
    if (t == 1023) g_rowptr[NN] = off;
}
__global__ void scatter_kernel(const int* __restrict__ src, const int* __restrict__ dst) {
    int e = blockIdx.x * blockDim.x + threadIdx.x;
    if (e < EE) {
        int d = dst[e];
        int p = atomicAdd(&g_cursor[d], 1);
        g_srcsorted[p] = src[e];
    }
}
__global__ void convh_kernel(const float* __restrict__ h) {
    size_t q = (size_t)blockIdx.x * blockDim.x + threadIdx.x;
    if (q >= (size_t)NN * TT * D / 4) return;
    float4 v = ((const float4*)h)[q];
    u16 h0, h1, h2, h3, l0, l1, l2, l3;
    bsplit(v.x, h0, l0); bsplit(v.y, h1, l1);
    bsplit(v.z, h2, l2); bsplit(v.w, h3, l3);
    ((uint2*)g_xhi)[q] = make_uint2((u32)h0 | ((u32)h1 << 16), (u32)h2 | ((u32)h3 << 16));
    ((uint2*)g_xlo)[q] = make_uint2((u32)l0 | ((u32)l1 << 16), (u32)l2 | ((u32)l3 << 16));
}
// LSTM weights: row_out j*4+g <- row_in g*128+j, cols [w_ih|w_hh]
__global__ void wlprep_kernel(const float* __restrict__ w_ih, const float* __restrict__ w_hh,
                              const float* __restrict__ b_ih, const float* __restrict__ b_hh) {
    int idx = blockIdx.x * blockDim.x + threadIdx.x;
    if (idx >= 512 * 256) return;
    int ro = idx >> 8, k = idx & 255;
    int ri = (ro & 3) * D + (ro >> 2);
    float v = (k < D) ? w_ih[ri * D + k] : w_hh[ri * D + (k - D)];
    u16 hh, ll;
    bsplit(v, hh, ll);
    g_wlhi[idx] = hh; g_wllo[idx] = ll;
    if (k == 0) g_biasp[ro] = b_ih[ri] + b_hh[ri];
}
// graph weights: B[n][k] = W[k][n]
__global__ void wgprep_kernel(const float* __restrict__ Wg1, const float* __restrict__ Wg2) {
    int idx = blockIdx.x * blockDim.x + threadIdx.x;
    if (idx >= 2 * 128 * 128) return;
    int sel = idx >> 14, e = idx & 16383;
    int n = e >> 7, k = e & 127;
    float v = sel ? Wg2[k * 128 + n] : Wg1[k * 128 + n];
    u16 hh, ll;
    bsplit(v, hh, ll);
    if (sel) { g_w2hi[e] = hh; g_w2lo[e] = ll; }
    else     { g_w1hi[e] = hh; g_w1lo[e] = ll; }
}

// ---------------- SpMM: emits bf16 hi/lo pairs ----------------
__global__ __launch_bounds__(256) void spmm_kernel(const float* __restrict__ X, int ldx) {
    int w = (blockIdx.x * blockDim.x + threadIdx.x) >> 5;
    int lane = threadIdx.x & 31;
    if (w >= NN) return;
    int s0 = g_rowptr[w], s1 = g_rowptr[w + 1];
    float4 acc = make_float4(0.f, 0.f, 0.f, 0.f);
    for (int base = s0; base < s1; base += 32) {
        int n = min(32, s1 - base);
        int s = 0; float ns = 0.f;
        if (lane < n) {
            s = g_srcsorted[base + lane];
            ns = g_norm_src[s];
        }
        for (int j = 0; j < n; j++) {
            int   sj = __shfl_sync(0xffffffffu, s, j);
            float nj = __shfl_sync(0xffffffffu, ns, j);
            float4 v = *(const float4*)(X + (size_t)sj * ldx + lane * 4);
            acc.x += v.x * nj; acc.y += v.y * nj;
            acc.z += v.z * nj; acc.w += v.w * nj;
        }
    }
    float nd = g_norm_dst[w];
    u16 h0, h1, h2, h3, l0, l1, l2, l3;
    bsplit(acc.x * nd, h0, l0); bsplit(acc.y * nd, h1, l1);
    bsplit(acc.z * nd, h2, l2); bsplit(acc.w * nd, h3, l3);
    size_t q = ((size_t)w * D + lane * 4) >> 2;
    ((uint2*)g_mhi)[q] = make_uint2((u32)h0 | ((u32)h1 << 16), (u32)h2 | ((u32)h3 << 16));
    ((uint2*)g_mlo)[q] = make_uint2((u32)l0 | ((u32)l1 << 16), (u32)l2 | ((u32)l3 << 16));
}

// ==================================================================================
// bf16 3-term split GEMM with legacy mma.m16n8k16. BM=128, BN=128, BK=16.
// 256 threads: 8 warps (2x4), warp tile 64x32 (4x4 m16n8 frags).
// Term-major mma issue: 16 independent accumulators between same-acc touches.
// MODE 0: graph conv, K=128: C = gelu(A@B^T + bias); opt C store, opt hs colsum.
// MODE 1: LSTM, K=256 (A = [x_t | h]): fused cell epilogue. grid.y = 4.
// ==================================================================================
template <int MODE>
__global__ __launch_bounds__(256) void gemm_bf16(
    const u32* __restrict__ A0h, const u32* __restrict__ A0l, int ldap,   // pairs/row
    const u32* __restrict__ A1h, const u32* __restrict__ A1l,             // MODE1 h (ld 64)
    const u32* __restrict__ Bh,  const u32* __restrict__ Bl,  int ldbp,
    const float* __restrict__ bias,
    float* __restrict__ C, float* __restrict__ hsacc,
    u16* __restrict__ hoh, u16* __restrict__ hol,
    float* __restrict__ hta)
{
    __shared__ __align__(16) u32 sh[8192];            // 32 KB
    u32* As_hi = sh;          // [8 frag][32 lane][4 reg]
    u32* As_lo = sh + 1024;
    u32* Bs_hi = sh + 2048;   // [16 frag][32 lane][2 reg]
    u32* Bs_lo = sh + 3072;
    float* gtile = (float*)sh;                        // epilogue [64][128]

    const int tid = threadIdx.x, lane = tid & 31;
    const int warpId = tid >> 5;
    const int warpM = warpId >> 2, warpN = warpId & 3;
    const int rowBase = blockIdx.x * 128;
    const int colBase = blockIdx.y * 128;

    float acc[4][4][4];
#pragma unroll
    for (int a = 0; a < 4; a++)
#pragma unroll
        for (int b = 0; b < 4; b++)
#pragma unroll
            for (int c = 0; c < 4; c++) acc[a][b][c] = 0.f;

    const int NCH = MODE ? 16 : 8;
    const int r_ = tid >> 1, halfk = (tid & 1) * 4;   // staging coords
    for (int ch = 0; ch < NCH; ch++) {
        // ---- stage A: 128 rows x 8 pairs, hi+lo ----
        {
            const u32 *sh_, *sl_;
            int po;
            if (MODE == 1 && ch >= 8) { sh_ = A1h; sl_ = A1l; po = (ch - 8) * 8 + halfk; }
            else                      { sh_ = A0h; sl_ = A0l; po = ch * 8 + halfk; }
            int ld = (MODE == 1 && ch >= 8) ? 64 : ldap;
            uint4 vh = make_uint4(0, 0, 0, 0), vl = vh;
            if (rowBase + r_ < NN) {
                vh = *(const uint4*)(sh_ + (size_t)(rowBase + r_) * ld + po);
                vl = *(const uint4*)(sl_ + (size_t)(rowBase + r_) * ld + po);
            }
            u32 ph[4] = {vh.x, vh.y, vh.z, vh.w};
            u32 pl[4] = {vl.x, vl.y, vl.z, vl.w};
            int m = r_ >> 4, row16 = r_ & 15;
#pragma unroll
            for (int j = 0; j < 4; j++) {
                int kp = halfk + j;
                int l = (row16 & 7) * 4 + (kp & 3);
                int rg = (row16 >> 3) | ((kp >> 2) << 1);
                int ad = (m * 32 + l) * 4 + rg;
                As_hi[ad] = ph[j];
                As_lo[ad] = pl[j];
            }
        }
        // ---- stage B: 128 cols x 8 pairs ----
        {
            int gc = (MODE ? colBase : 0) + r_;
            int po = ch * 8 + halfk;
            uint4 vh = *(const uint4*)(Bh + (size_t)gc * ldbp + po);
            uint4 vl = *(const uint4*)(Bl + (size_t)gc * ldbp + po);
            u32 ph[4] = {vh.x, vh.y, vh.z, vh.w};
            u32 pl[4] = {vl.x, vl.y, vl.z, vl.w};
            int n = r_ >> 3;
#pragma unroll
            for (int j = 0; j < 4; j++) {
                int kp = halfk + j;
                int l = (r_ & 7) * 4 + (kp & 3);
                int rg = kp >> 2;
                int ad = (n * 32 + l) * 2 + rg;
                Bs_hi[ad] = ph[j];
                Bs_lo[ad] = pl[j];
            }
        }
        __syncthreads();
        // ---- compute: load all frags, then term-major mma (no RAW chains) ----
        uint4 ah[4], al[4];
        uint2 bh[4], bl[4];
#pragma unroll
        for (int mi = 0; mi < 4; mi++) {
            int fid = warpM * 4 + mi;
            ah[mi] = ((const uint4*)As_hi)[fid * 32 + lane];
            al[mi] = ((const uint4*)As_lo)[fid * 32 + lane];
        }
#pragma unroll
        for (int ni = 0; ni < 4; ni++) {
            int fid = warpN * 4 + ni;
            bh[ni] = ((const uint2*)Bs_hi)[fid * 32 + lane];
            bl[ni] = ((const uint2*)Bs_lo)[fid * 32 + lane];
        }
#pragma unroll
        for (int ni = 0; ni < 4; ni++)
#pragma unroll
            for (int mi = 0; mi < 4; mi++)
                mma16(acc[mi][ni], ah[mi], bh[ni].x, bh[ni].y);
#pragma unroll
        for (int ni = 0; ni < 4; ni++)
#pragma unroll
            for (int mi = 0; mi < 4; mi++)
                mma16(acc[mi][ni], ah[mi], bl[ni].x, bl[ni].y);
#pragma unroll
        for (int ni = 0; ni < 4; ni++)
#pragma unroll
            for (int mi = 0; mi < 4; mi++)
                mma16(acc[mi][ni], al[mi], bh[ni].x, bh[ni].y);
        __syncthreads();
    }

    // ---- epilogue: stage through shared, 2 row-halves of 64 ----
    float csum[4] = {0.f, 0.f, 0.f, 0.f};
    const int cq = tid & 31;

    for (int half = 0; half < 2; half++) {
        __syncthreads();
        if (warpM == half) {
#pragma unroll
            for (int mi = 0; mi < 4; mi++) {
#pragma unroll
                for (int ni = 0; ni < 4; ni++) {
                    int rloc = mi * 16 + (lane >> 2);
                    int cloc = warpN * 32 + ni * 8 + (lane & 3) * 2;
                    float b0v = bias[colBase + cloc];
                    float b1v = bias[colBase + cloc + 1];
                    gtile[rloc * 128 + cloc]           = acc[mi][ni][0] + b0v;
                    gtile[rloc * 128 + cloc + 1]       = acc[mi][ni][1] + b1v;
                    gtile[(rloc + 8) * 128 + cloc]     = acc[mi][ni][2] + b0v;
                    gtile[(rloc + 8) * 128 + cloc + 1] = acc[mi][ni][3] + b1v;
                }
            }
        }
        __syncthreads();
#pragma unroll
        for (int i = 0; i < 8; i++) {
            int e = tid + i * 256;
            int rloc = e >> 5;
            int row = rowBase + half * 64 + rloc;
            if (MODE == 0) {
                float4 gv = *(const float4*)&gtile[rloc * 128 + cq * 4];
                float4 ov;
                ov.x = gelu_exact(gv.x);
                ov.y = gelu_exact(gv.y);
                ov.z = gelu_exact(gv.z);
                ov.w = gelu_exact(gv.w);
                if (row < NN) {
                    if (C != nullptr)
                        *(float4*)(C + (size_t)row * D + cq * 4) = ov;
                    csum[0] += ov.x; csum[1] += ov.y; csum[2] += ov.z; csum[3] += ov.w;
                }
            } else {
                if (row < NN) {
                    float4 gv = *(const float4*)&gtile[rloc * 128 + cq * 4];
                    int fg = blockIdx.y * 32 + cq;
                    size_t idx = (size_t)row * D + fg;
                    float cp = g_c[idx];
                    float cn = sigmoidf_(gv.y) * cp + sigmoidf_(gv.x) * tanhf(gv.z);
                    float ho = sigmoidf_(gv.w) * tanhf(cn);
                    g_c[idx] = cn;
                    hta[idx] += ho;
                    u16 hh, hl;
                    bsplit(ho, hh, hl);
                    hoh[idx] = hh;
                    hol[idx] = hl;
                }
            }
        }
    }
    if (MODE == 0 && hsacc != nullptr) {
#pragma unroll
        for (int j = 0; j < 4; j++) atomicAdd(&hsacc[cq * 4 + j], csum[j]);
    }
}

__global__ void finalize_kernel(float* __restrict__ out) {
    int idx = blockIdx.x * blockDim.x + threadIdx.x;
    if (idx < TT * D) out[idx] = g_hs[idx] * (1.0f / (float)NN);
    if (idx < NN * D) out[TT * D + idx] *= (1.0f / (float)TT);
}

// ---------------- launch ----------------
extern "C" void kernel_launch(void* const* d_in, const int* in_sizes, int n_in,
                              void* d_out, int out_size) {
    const float* h    = (const float*)d_in[0];
    const int*   src  = (const int*)d_in[1];
    const int*   dst  = (const int*)d_in[2];
    const float* Wg1  = (const float*)d_in[3];
    const float* bg1  = (const float*)d_in[4];
    const float* Wg2  = (const float*)d_in[5];
    const float* bg2  = (const float*)d_in[6];
    const float* w_ih = (const float*)d_in[7];
    const float* w_hh = (const float*)d_in[8];
    const float* b_ih = (const float*)d_in[9];
    const float* b_hh = (const float*)d_in[10];

    float* out    = (float*)d_out;
    float* out_ht = out + TT * D;

    u16 *pxhi, *pxlo, *pmhi, *pmlo, *ph0h, *ph0l, *ph1h, *ph1l;
    u16 *pwlh, *pwll, *pw1h, *pw1l, *pw2h, *pw2l;
    float *pxact, *pbp, *phs;
    cudaGetSymbolAddress((void**)&pxhi, g_xhi);
    cudaGetSymbolAddress((void**)&pxlo, g_xlo);
    cudaGetSymbolAddress((void**)&pmhi, g_mhi);
    cudaGetSymbolAddress((void**)&pmlo, g_mlo);
    cudaGetSymbolAddress((void**)&ph0h, g_hhi0);
    cudaGetSymbolAddress((void**)&ph0l, g_hlo0);
    cudaGetSymbolAddress((void**)&ph1h, g_hhi1);
    cudaGetSymbolAddress((void**)&ph1l, g_hlo1);
    cudaGetSymbolAddress((void**)&pwlh, g_wlhi);
    cudaGetSymbolAddress((void**)&pwll, g_wllo);
    cudaGetSymbolAddress((void**)&pw1h, g_w1hi);
    cudaGetSymbolAddress((void**)&pw1l, g_w1lo);
    cudaGetSymbolAddress((void**)&pw2h, g_w2hi);
    cudaGetSymbolAddress((void**)&pw2l, g_w2lo);
    cudaGetSymbolAddress((void**)&pxact, g_xact);
    cudaGetSymbolAddress((void**)&pbp, g_biasp);
    cudaGetSymbolAddress((void**)&phs, g_hs);

    // fork/join resources (host objects only)
    cudaStream_t s2;
    cudaStreamCreateWithFlags(&s2, cudaStreamNonBlocking);
    cudaEvent_t e1, e2;
    cudaEventCreateWithFlags(&e1, cudaEventDisableTiming);
    cudaEventCreateWithFlags(&e2, cudaEventDisableTiming);

    // common setup on main stream
    init_kernel<<<(NN * D + 255) / 256, 256>>>(out_ht);
    wlprep_kernel<<<(512 * 256 + 255) / 256, 256>>>(w_ih, w_hh, b_ih, b_hh);
    convh_kernel<<<(int)(((size_t)NN * TT * D / 4 + 255) / 256), 256>>>(h);

    // fork: LSTM chain on s2
    cudaEventRecord(e1, 0);
    cudaStreamWaitEvent(s2, e1, 0);

    const int gx = (NN + 127) / 128;   // 391
    u16 *hih = ph0h, *hil = ph0l, *hoh = ph1h, *hol = ph1l;
    for (int t = 0; t < TT; t++) {
        gemm_bf16<1><<<dim3(gx, 4), 256, 0, s2>>>(
            (u32*)pxhi + (size_t)t * 64, (u32*)pxlo + (size_t)t * 64, TT * 64,
            (u32*)hih, (u32*)hil,
            (u32*)pwlh, (u32*)pwll, 128, pbp,
            nullptr, nullptr, hoh, hol, out_ht);
        u16* t1 = hih; hih = hoh; hoh = t1;
        u16* t2 = hil; hil = hol; hol = t2;
    }
    cudaEventRecord(e2, s2);

    // graph chain on main stream
    hist_kernel<<<(EE + 255) / 256, 256>>>(src, dst);
    norm_kernel<<<(NN + 255) / 256, 256>>>();
    wgprep_kernel<<<(2 * 128 * 128 + 255) / 256, 256>>>(Wg1, Wg2);
    scan_kernel<<<1, 1024>>>();
    scatter_kernel<<<(EE + 255) / 256, 256>>>(src, dst);

    int spmm_blocks = (NN * 32 + 255) / 256;
    for (int t = 0; t < TT; t++) {
        spmm_kernel<<<spmm_blocks, 256>>>(h + t * D, TT * D);
        gemm_bf16<0><<<dim3(gx, 1), 256>>>((u32*)pmhi, (u32*)pmlo, 64, nullptr, nullptr,
                                           (u32*)pw1h, (u32*)pw1l, 64, bg1,
                                           pxact, nullptr, nullptr, nullptr, nullptr);
        spmm_kernel<<<spmm_blocks, 256>>>(pxact, D);
        gemm_bf16<0><<<dim3(gx, 1), 256>>>((u32*)pmhi, (u32*)pmlo, 64, nullptr, nullptr,
                                           (u32*)pw2h, (u32*)pw2l, 64, bg2,
                                           nullptr, phs + t * D, nullptr, nullptr, nullptr);
    }

    // join and finalize
    cudaStreamWaitEvent(0, e2, 0);
    finalize_kernel<<<(NN * D + 255) / 256, 256>>>(out);
}

// round 10
// speedup vs baseline: 1.3273x; 1.0762x over previous
#include <cuda_runtime.h>
#include <cuda_bf16.h>
#include <math.h>
#include <stdint.h>

#define NN 50000
#define EE 800000
#define TT 12
#define D  128

typedef unsigned short u16;
typedef unsigned int   u32;

// ---------------- scratch ----------------
__device__ float g_norm_src[NN], g_norm_dst[NN];
__device__ int g_ocnt[NN], g_cnt[NN + 1], g_rowptr[NN + 1], g_cursor[NN];
__device__ int g_srcsorted[EE];
__device__ __align__(16) u16 g_xhi[(size_t)NN * TT * D];   // h pre-split (pair-packed along k)
__device__ __align__(16) u16 g_xlo[(size_t)NN * TT * D];
__device__ __align__(16) u16 g_mhi[(size_t)NN * D];        // spmm out
__device__ __align__(16) u16 g_mlo[(size_t)NN * D];
__device__ __align__(16) float g_xact[(size_t)NN * D];     // layer-1 act (fp32, spmm2 input)
__device__ __align__(16) u16 g_hhi0[(size_t)NN * D], g_hlo0[(size_t)NN * D];
__device__ __align__(16) u16 g_hhi1[(size_t)NN * D], g_hlo1[(size_t)NN * D];
__device__ __align__(16) float g_c[(size_t)NN * D];
__device__ __align__(16) u16 g_wlhi[512 * 256], g_wllo[512 * 256];  // [n][k], quad-permuted rows
__device__ __align__(16) u16 g_w1hi[128 * 128], g_w1lo[128 * 128];  // [n][k]
__device__ __align__(16) u16 g_w2hi[128 * 128], g_w2lo[128 * 128];
__device__ float g_biasp[512];
__device__ float g_hs[TT * D];

// ---------------- helpers ----------------
__device__ __forceinline__ float gelu_exact(float v) {
    return 0.5f * v * (1.0f + erff(v * 0.70710678118654752f));
}
__device__ __forceinline__ float sigmoidf_(float v) {
    return 1.0f / (1.0f + __expf(-v));
}
__device__ __forceinline__ void bsplit(float x, u16& h, u16& l) {
    __nv_bfloat16 bh = __float2bfloat16(x);
    float hr = __bfloat162float(bh);
    __nv_bfloat16 bl = __float2bfloat16(x - hr);
    h = *(u16*)&bh;
    l = *(u16*)&bl;
}
__device__ __forceinline__ u32 smem_u32(const void* p) {
    u32 a;
    asm("{ .reg .u64 t; cvta.to.shared.u64 t, %1; cvt.u32.u64 %0, t; }" : "=r"(a) : "l"(p));
    return a;
}
__device__ __forceinline__ void mma16(float (&c)[4], uint4 a, u32 b0, u32 b1) {
    asm volatile(
        "mma.sync.aligned.m16n8k16.row.col.f32.bf16.bf16.f32 "
        "{%0,%1,%2,%3},{%4,%5,%6,%7},{%8,%9},{%0,%1,%2,%3};\n"
        : "+f"(c[0]), "+f"(c[1]), "+f"(c[2]), "+f"(c[3])
        : "r"(a.x), "r"(a.y), "r"(a.z), "r"(a.w), "r"(b0), "r"(b1));
}
#define LDSM_X4(d, a) \
    asm volatile("ldmatrix.sync.aligned.m8n8.x4.shared.b16 {%0,%1,%2,%3}, [%4];" \
                 : "=r"((d).x), "=r"((d).y), "=r"((d).z), "=r"((d).w) : "r"(a))
#define LDSM_X2(d, a) \
    asm volatile("ldmatrix.sync.aligned.m8n8.x2.shared.b16 {%0,%1}, [%2];" \
                 : "=r"((d).x), "=r"((d).y) : "r"(a))
// swizzled byte offset inside a 128-row x 32B tile
__device__ __forceinline__ u32 swz(int row, int half) {
    return (u32)(row * 32 + ((half << 4) ^ ((row & 4) << 2)));
}

// ---------------- setup kernels ----------------
__global__ void init_kernel(float* __restrict__ out_ht) {
    int i = blockIdx.x * blockDim.x + threadIdx.x;
    if (i < NN * D) {
        g_c[i] = 0.0f;
        g_hhi0[i] = 0; g_hlo0[i] = 0;
        out_ht[i] = 0.0f;
    }
    if (i < NN) { g_ocnt[i] = 0; g_cnt[i] = 0; }
    if (i == 0) g_cnt[NN] = 0;
    if (i < TT * D) g_hs[i] = 0.0f;
}
__global__ void hist_kernel(const int* __restrict__ src, const int* __restrict__ dst) {
    int e = blockIdx.x * blockDim.x + threadIdx.x;
    if (e < EE) {
        atomicAdd(&g_ocnt[src[e]], 1);
        atomicAdd(&g_cnt[dst[e]], 1);
    }
}
__global__ void norm_kernel() {
    int i = blockIdx.x * blockDim.x + threadIdx.x;
    if (i < NN) {
        g_norm_src[i] = rsqrtf(fmaxf((float)g_ocnt[i], 1.0f));
        g_norm_dst[i] = rsqrtf(fmaxf((float)g_cnt[i], 1.0f));
    }
}
__global__ void scan_kernel() {
    __shared__ int ps[1024];
    const int CH = (NN + 1023) / 1024;
    int t = threadIdx.x;
    int beg = t * CH, end = min(beg + CH, NN);
    int s = 0;
    for (int i = beg; i < end; i++) s += g_cnt[i];
    ps[t] = s;
    __syncthreads();
    if (t == 0) {
        int a = 0;
        for (int i = 0; i < 1024; i++) { int v = ps[i]; ps[i] = a; a += v; }
    }
    __syncthreads();
    int off = ps[t];
    for (int i = beg; i < end; i++) {
        g_rowptr[i] = off;
        g_cursor[i] = off;
        off += g_cnt[i];
    }
    if (t == 1023) g_rowptr[NN] = off;
}
__global__ void scatter_kernel(const int* __restrict__ src, const int* __restrict__ dst) {
    int e = blockIdx.x * blockDim.x + threadIdx.x;
    if (e < EE) {
        int d = dst[e];
        int p = atomicAdd(&g_cursor[d], 1);
        g_srcsorted[p] = src[e];
    }
}
__global__ void convh_kernel(const float* __restrict__ h) {
    size_t q = (size_t)blockIdx.x * blockDim.x + threadIdx.x;
    if (q >= (size_t)NN * TT * D / 4) return;
    float4 v = ((const float4*)h)[q];
    u16 h0, h1, h2, h3, l0, l1, l2, l3;
    bsplit(v.x, h0, l0); bsplit(v.y, h1, l1);
    bsplit(v.z, h2, l2); bsplit(v.w, h3, l3);
    ((uint2*)g_xhi)[q] = make_uint2((u32)h0 | ((u32)h1 << 16), (u32)h2 | ((u32)h3 << 16));
    ((uint2*)g_xlo)[q] = make_uint2((u32)l0 | ((u32)l1 << 16), (u32)l2 | ((u32)l3 << 16));
}
// LSTM weights: row_out j*4+g <- row_in g*128+j, cols [w_ih|w_hh]
__global__ void wlprep_kernel(const float* __restrict__ w_ih, const float* __restrict__ w_hh,
                              const float* __restrict__ b_ih, const float* __restrict__ b_hh) {
    int idx = blockIdx.x * blockDim.x + threadIdx.x;
    if (idx >= 512 * 256) return;
    int ro = idx >> 8, k = idx & 255;
    int ri = (ro & 3) * D + (ro >> 2);
    float v = (k < D) ? w_ih[ri * D + k] : w_hh[ri * D + (k - D)];
    u16 hh, ll;
    bsplit(v, hh, ll);
    g_wlhi[idx] = hh; g_wllo[idx] = ll;
    if (k == 0) g_biasp[ro] = b_ih[ri] + b_hh[ri];
}
// graph weights: B[n][k] = W[k][n]
__global__ void wgprep_kernel(const float* __restrict__ Wg1, const float* __restrict__ Wg2) {
    int idx = blockIdx.x * blockDim.x + threadIdx.x;
    if (idx >= 2 * 128 * 128) return;
    int sel = idx >> 14, e = idx & 16383;
    int n = e >> 7, k = e & 127;
    float v = sel ? Wg2[k * 128 + n] : Wg1[k * 128 + n];
    u16 hh, ll;
    bsplit(v, hh, ll);
    if (sel) { g_w2hi[e] = hh; g_w2lo[e] = ll; }
    else     { g_w1hi[e] = hh; g_w1lo[e] = ll; }
}

// ---------------- SpMM: emits bf16 hi/lo pairs ----------------
__global__ __launch_bounds__(256) void spmm_kernel(const float* __restrict__ X, int ldx) {
    int w = (blockIdx.x * blockDim.x + threadIdx.x) >> 5;
    int lane = threadIdx.x & 31;
    if (w >= NN) return;
    int s0 = g_rowptr[w], s1 = g_rowptr[w + 1];
    float4 acc = make_float4(0.f, 0.f, 0.f, 0.f);
    for (int base = s0; base < s1; base += 32) {
        int n = min(32, s1 - base);
        int s = 0; float ns = 0.f;
        if (lane < n) {
            s = g_srcsorted[base + lane];
            ns = g_norm_src[s];
        }
        for (int j = 0; j < n; j++) {
            int   sj = __shfl_sync(0xffffffffu, s, j);
            float nj = __shfl_sync(0xffffffffu, ns, j);
            float4 v = *(const float4*)(X + (size_t)sj * ldx + lane * 4);
            acc.x += v.x * nj; acc.y += v.y * nj;
            acc.z += v.z * nj; acc.w += v.w * nj;
        }
    }
    float nd = g_norm_dst[w];
    u16 h0, h1, h2, h3, l0, l1, l2, l3;
    bsplit(acc.x * nd, h0, l0); bsplit(acc.y * nd, h1, l1);
    bsplit(acc.z * nd, h2, l2); bsplit(acc.w * nd, h3, l3);
    size_t q = ((size_t)w * D + lane * 4) >> 2;
    ((uint2*)g_mhi)[q] = make_uint2((u32)h0 | ((u32)h1 << 16), (u32)h2 | ((u32)h3 << 16));
    ((uint2*)g_mlo)[q] = make_uint2((u32)l0 | ((u32)l1 << 16), (u32)l2 | ((u32)l3 << 16));
}

// ==================================================================================
// bf16 3-term split GEMM, mma.m16n8k16, BM=128 BN=128 BK=16.
// Row-major swizzled SMEM staging (STS.128) + ldmatrix fragment loads.
// Term-major mma issue (no accumulator RAW chains).
// MODE 0: graph conv, K=128: C = gelu(A@B^T + bias); opt C store, opt hs colsum.
// MODE 1: LSTM, K=256 (A = [x_t | h]): fused cell epilogue. grid.y = 4.
// ==================================================================================
template <int MODE>
__global__ __launch_bounds__(256) void gemm_bf16(
    const u32* __restrict__ A0h, const u32* __restrict__ A0l, int ldap,   // pairs/row
    const u32* __restrict__ A1h, const u32* __restrict__ A1l,             // MODE1 h (ld 64)
    const u32* __restrict__ Bh,  const u32* __restrict__ Bl,  int ldbp,
    const float* __restrict__ bias,
    float* __restrict__ C, float* __restrict__ hsacc,
    u16* __restrict__ hoh, u16* __restrict__ hol,
    float* __restrict__ hta)
{
    __shared__ __align__(16) u32 sh[8192];   // staging uses first 16KB; epilogue 32KB
    float* gtile = (float*)sh;               // epilogue [64][128]

    const int tid = threadIdx.x, lane = tid & 31;
    const int warpId = tid >> 5;
    const int warpM = warpId >> 2, warpN = warpId & 3;
    const int rowBase = blockIdx.x * 128;
    const int colBase = blockIdx.y * 128;

    const u32 smb = smem_u32(sh);
    const u32 smA_hi = smb;              // 128 rows x 32B
    const u32 smA_lo = smb + 4096;
    const u32 smB_hi = smb + 8192;       // 128 n-rows x 32B
    const u32 smB_lo = smb + 12288;

    float acc[4][4][4];
#pragma unroll
    for (int a = 0; a < 4; a++)
#pragma unroll
        for (int b = 0; b < 4; b++)
#pragma unroll
            for (int c = 0; c < 4; c++) acc[a][b][c] = 0.f;

    const int NCH = MODE ? 16 : 8;
    const int r_ = tid >> 1, half_ = tid & 1;        // staging coords
    const u32 stA = swz(r_, half_);                  // store offsets (constant over chunks)

    for (int ch = 0; ch < NCH; ch++) {
        // ---- stage A (row-major swizzled, one STS.128 each for hi/lo) ----
        {
            const u32 *sh_, *sl_;
            int po;
            if (MODE == 1 && ch >= 8) { sh_ = A1h; sl_ = A1l; po = (ch - 8) * 8 + half_ * 4; }
            else                      { sh_ = A0h; sl_ = A0l; po = ch * 8 + half_ * 4; }
            int ld = (MODE == 1 && ch >= 8) ? 64 : ldap;
            uint4 vh = make_uint4(0, 0, 0, 0), vl = vh;
            if (rowBase + r_ < NN) {
                vh = *(const uint4*)(sh_ + (size_t)(rowBase + r_) * ld + po);
                vl = *(const uint4*)(sl_ + (size_t)(rowBase + r_) * ld + po);
            }
            asm volatile("st.shared.v4.b32 [%0], {%1,%2,%3,%4};" ::
                         "r"(smA_hi + stA), "r"(vh.x), "r"(vh.y), "r"(vh.z), "r"(vh.w));
            asm volatile("st.shared.v4.b32 [%0], {%1,%2,%3,%4};" ::
                         "r"(smA_lo + stA), "r"(vl.x), "r"(vl.y), "r"(vl.z), "r"(vl.w));
        }
        // ---- stage B ----
        {
            int gc = (MODE ? colBase : 0) + r_;
            int po = ch * 8 + half_ * 4;
            uint4 vh = *(const uint4*)(Bh + (size_t)gc * ldbp + po);
            uint4 vl = *(const uint4*)(Bl + (size_t)gc * ldbp + po);
            asm volatile("st.shared.v4.b32 [%0], {%1,%2,%3,%4};" ::
                         "r"(smB_hi + stA), "r"(vh.x), "r"(vh.y), "r"(vh.z), "r"(vh.w));
            asm volatile("st.shared.v4.b32 [%0], {%1,%2,%3,%4};" ::
                         "r"(smB_lo + stA), "r"(vl.x), "r"(vl.y), "r"(vl.z), "r"(vl.w));
        }
        __syncthreads();
        // ---- fragment loads via ldmatrix ----
        uint4 ah[4], al[4];
        uint2 bh[4], bl[4];
        {
            int ra = lane & 15, ha = lane >> 4;
#pragma unroll
            for (int mi = 0; mi < 4; mi++) {
                int row = warpM * 64 + mi * 16 + ra;
                u32 off = swz(row, ha);
                LDSM_X4(ah[mi], smA_hi + off);
                LDSM_X4(al[mi], smA_lo + off);
            }
            int rb = lane & 7, hb = (lane >> 3) & 1;
#pragma unroll
            for (int ni = 0; ni < 4; ni++) {
                int n = warpN * 32 + ni * 8 + rb;
                u32 off = swz(n, hb);
                LDSM_X2(bh[ni], smB_hi + off);
                LDSM_X2(bl[ni], smB_lo + off);
            }
        }
        // ---- term-major mma (16 independent accs between same-acc touches) ----
#pragma unroll
        for (int ni = 0; ni < 4; ni++)
#pragma unroll
            for (int mi = 0; mi < 4; mi++)
                mma16(acc[mi][ni], ah[mi], bh[ni].x, bh[ni].y);
#pragma unroll
        for (int ni = 0; ni < 4; ni++)
#pragma unroll
            for (int mi = 0; mi < 4; mi++)
                mma16(acc[mi][ni], ah[mi], bl[ni].x, bl[ni].y);
#pragma unroll
        for (int ni = 0; ni < 4; ni++)
#pragma unroll
            for (int mi = 0; mi < 4; mi++)
                mma16(acc[mi][ni], al[mi], bh[ni].x, bh[ni].y);
        __syncthreads();
    }

    // ---- epilogue: stage through shared, 2 row-halves of 64 ----
    float csum[4] = {0.f, 0.f, 0.f, 0.f};
    const int cq = tid & 31;

    for (int half = 0; half < 2; half++) {
        __syncthreads();
        if (warpM == half) {
#pragma unroll
            for (int mi = 0; mi < 4; mi++) {
#pragma unroll
                for (int ni = 0; ni < 4; ni++) {
                    int rloc = mi * 16 + (lane >> 2);
                    int cloc = warpN * 32 + ni * 8 + (lane & 3) * 2;
                    float b0v = bias[colBase + cloc];
                    float b1v = bias[colBase + cloc + 1];
                    gtile[rloc * 128 + cloc]           = acc[mi][ni][0] + b0v;
                    gtile[rloc * 128 + cloc + 1]       = acc[mi][ni][1] + b1v;
                    gtile[(rloc + 8) * 128 + cloc]     = acc[mi][ni][2] + b0v;
                    gtile[(rloc + 8) * 128 + cloc + 1] = acc[mi][ni][3] + b1v;
                }
            }
        }
        __syncthreads();
#pragma unroll
        for (int i = 0; i < 8; i++) {
            int e = tid + i * 256;
            int rloc = e >> 5;
            int row = rowBase + half * 64 + rloc;
            if (MODE == 0) {
                float4 gv = *(const float4*)&gtile[rloc * 128 + cq * 4];
                float4 ov;
                ov.x = gelu_exact(gv.x);
                ov.y = gelu_exact(gv.y);
                ov.z = gelu_exact(gv.z);
                ov.w = gelu_exact(gv.w);
                if (row < NN) {
                    if (C != nullptr)
                        *(float4*)(C + (size_t)row * D + cq * 4) = ov;
                    csum[0] += ov.x; csum[1] += ov.y; csum[2] += ov.z; csum[3] += ov.w;
                }
            } else {
                if (row < NN) {
                    float4 gv = *(const float4*)&gtile[rloc * 128 + cq * 4];
                    int fg = blockIdx.y * 32 + cq;
                    size_t idx = (size_t)row * D + fg;
                    float cp = g_c[idx];
                    float cn = sigmoidf_(gv.y) * cp + sigmoidf_(gv.x) * tanhf(gv.z);
                    float ho = sigmoidf_(gv.w) * tanhf(cn);
                    g_c[idx] = cn;
                    hta[idx] += ho;
                    u16 hh, hl;
                    bsplit(ho, hh, hl);
                    hoh[idx] = hh;
                    hol[idx] = hl;
                }
            }
        }
    }
    if (MODE == 0 && hsacc != nullptr) {
#pragma unroll
        for (int j = 0; j < 4; j++) atomicAdd(&hsacc[cq * 4 + j], csum[j]);
    }
}

__global__ void finalize_kernel(float* __restrict__ out) {
    int idx = blockIdx.x * blockDim.x + threadIdx.x;
    if (idx < TT * D) out[idx] = g_hs[idx] * (1.0f / (float)NN);
    if (idx < NN * D) out[TT * D + idx] *= (1.0f / (float)TT);
}

// ---------------- launch ----------------
extern "C" void kernel_launch(void* const* d_in, const int* in_sizes, int n_in,
                              void* d_out, int out_size) {
    const float* h    = (const float*)d_in[0];
    const int*   src  = (const int*)d_in[1];
    const int*   dst  = (const int*)d_in[2];
    const float* Wg1  = (const float*)d_in[3];
    const float* bg1  = (const float*)d_in[4];
    const float* Wg2  = (const float*)d_in[5];
    const float* bg2  = (const float*)d_in[6];
    const float* w_ih = (const float*)d_in[7];
    const float* w_hh = (const float*)d_in[8];
    const float* b_ih = (const float*)d_in[9];
    const float* b_hh = (const float*)d_in[10];

    float* out    = (float*)d_out;
    float* out_ht = out + TT * D;

    u16 *pxhi, *pxlo, *pmhi, *pmlo, *ph0h, *ph0l, *ph1h, *ph1l;
    u16 *pwlh, *pwll, *pw1h, *pw1l, *pw2h, *pw2l;
    float *pxact, *pbp, *phs;
    cudaGetSymbolAddress((void**)&pxhi, g_xhi);
    cudaGetSymbolAddress((void**)&pxlo, g_xlo);
    cudaGetSymbolAddress((void**)&pmhi, g_mhi);
    cudaGetSymbolAddress((void**)&pmlo, g_mlo);
    cudaGetSymbolAddress((void**)&ph0h, g_hhi0);
    cudaGetSymbolAddress((void**)&ph0l, g_hlo0);
    cudaGetSymbolAddress((void**)&ph1h, g_hhi1);
    cudaGetSymbolAddress((void**)&ph1l, g_hlo1);
    cudaGetSymbolAddress((void**)&pwlh, g_wlhi);
    cudaGetSymbolAddress((void**)&pwll, g_wllo);
    cudaGetSymbolAddress((void**)&pw1h, g_w1hi);
    cudaGetSymbolAddress((void**)&pw1l, g_w1lo);
    cudaGetSymbolAddress((void**)&pw2h, g_w2hi);
    cudaGetSymbolAddress((void**)&pw2l, g_w2lo);
    cudaGetSymbolAddress((void**)&pxact, g_xact);
    cudaGetSymbolAddress((void**)&pbp, g_biasp);
    cudaGetSymbolAddress((void**)&phs, g_hs);

    // fork/join resources (host objects only)
    cudaStream_t s2;
    cudaStreamCreateWithFlags(&s2, cudaStreamNonBlocking);
    cudaEvent_t e1, e2;
    cudaEventCreateWithFlags(&e1, cudaEventDisableTiming);
    cudaEventCreateWithFlags(&e2, cudaEventDisableTiming);

    // common setup on main stream
    init_kernel<<<(NN * D + 255) / 256, 256>>>(out_ht);
    wlprep_kernel<<<(512 * 256 + 255) / 256, 256>>>(w_ih, w_hh, b_ih, b_hh);
    convh_kernel<<<(int)(((size_t)NN * TT * D / 4 + 255) / 256), 256>>>(h);

    // fork: LSTM chain on s2
    cudaEventRecord(e1, 0);
    cudaStreamWaitEvent(s2, e1, 0);

    const int gx = (NN + 127) / 128;   // 391
    u16 *hih = ph0h, *hil = ph0l, *hoh = ph1h, *hol = ph1l;
    for (int t = 0; t < TT; t++) {
        gemm_bf16<1><<<dim3(gx, 4), 256, 0, s2>>>(
            (u32*)pxhi + (size_t)t * 64, (u32*)pxlo + (size_t)t * 64, TT * 64,
            (u32*)hih, (u32*)hil,
            (u32*)pwlh, (u32*)pwll, 128, pbp,
            nullptr, nullptr, hoh, hol, out_ht);
        u16* t1 = hih; hih = hoh; hoh = t1;
        u16* t2 = hil; hil = hol; hol = t2;
    }
    cudaEventRecord(e2, s2);

    // graph chain on main stream
    hist_kernel<<<(EE + 255) / 256, 256>>>(src, dst);
    norm_kernel<<<(NN + 255) / 256, 256>>>();
    wgprep_kernel<<<(2 * 128 * 128 + 255) / 256, 256>>>(Wg1, Wg2);
    scan_kernel<<<1, 1024>>>();
    scatter_kernel<<<(EE + 255) / 256, 256>>>(src, dst);

    int spmm_blocks = (NN * 32 + 255) / 256;
    for (int t = 0; t < TT; t++) {
        spmm_kernel<<<spmm_blocks, 256>>>(h + t * D, TT * D);
        gemm_bf16<0><<<dim3(gx, 1), 256>>>((u32*)pmhi, (u32*)pmlo, 64, nullptr, nullptr,
                                           (u32*)pw1h, (u32*)pw1l, 64, bg1,
                                           pxact, nullptr, nullptr, nullptr, nullptr);
        spmm_kernel<<<spmm_blocks, 256>>>(pxact, D);
        gemm_bf16<0><<<dim3(gx, 1), 256>>>((u32*)pmhi, (u32*)pmlo, 64, nullptr, nullptr,
                                           (u32*)pw2h, (u32*)pw2l, 64, bg2,
                                           nullptr, phs + t * D, nullptr, nullptr, nullptr);
    }

    // join and finalize
    cudaStreamWaitEvent(0, e2, 0);
    finalize_kernel<<<(NN * D + 255) / 256, 256>>>(out);
}

// round 11
// speedup vs baseline: 1.4245x; 1.0732x over previous
#include <cuda_runtime.h>
#include <cuda_bf16.h>
#include <math.h>
#include <stdint.h>

#define NN 50000
#define EE 800000
#define TT 12
#define D  128

typedef unsigned short u16;
typedef unsigned int   u32;

// ---------------- scratch ----------------
__device__ float g_norm_src[NN], g_norm_dst[NN];
__device__ int g_ocnt[NN], g_cnt[NN + 1], g_rowptr[NN + 1], g_cursor[NN];
__device__ int g_srcsorted[EE];
__device__ __align__(16) u16 g_xhi[(size_t)NN * TT * D];   // h pre-split (pair-packed along k)
__device__ __align__(16) u16 g_xlo[(size_t)NN * TT * D];
__device__ __align__(16) u16 g_mhi[(size_t)NN * D];        // spmm out
__device__ __align__(16) u16 g_mlo[(size_t)NN * D];
__device__ __align__(16) float g_xact[(size_t)NN * D];     // layer-1 act (fp32, spmm2 input)
__device__ __align__(16) u16 g_hhi0[(size_t)NN * D], g_hlo0[(size_t)NN * D];
__device__ __align__(16) u16 g_hhi1[(size_t)NN * D], g_hlo1[(size_t)NN * D];
__device__ __align__(16) float g_c[(size_t)NN * D];
__device__ __align__(16) u16 g_wlhi[512 * 256], g_wllo[512 * 256];  // [n][k], quad-permuted rows
__device__ __align__(16) u16 g_w1hi[128 * 128], g_w1lo[128 * 128];  // [n][k]
__device__ __align__(16) u16 g_w2hi[128 * 128], g_w2lo[128 * 128];
__device__ float g_biasp[512];
__device__ float g_hs[TT * D];

// ---------------- helpers ----------------
__device__ __forceinline__ float gelu_exact(float v) {
    return 0.5f * v * (1.0f + erff(v * 0.70710678118654752f));
}
__device__ __forceinline__ float sigmoidf_(float v) {
    return 1.0f / (1.0f + __expf(-v));
}
__device__ __forceinline__ void bsplit(float x, u16& h, u16& l) {
    __nv_bfloat16 bh = __float2bfloat16(x);
    float hr = __bfloat162float(bh);
    __nv_bfloat16 bl = __float2bfloat16(x - hr);
    h = *(u16*)&bh;
    l = *(u16*)&bl;
}
__device__ __forceinline__ u32 smem_u32(const void* p) {
    u32 a;
    asm("{ .reg .u64 t; cvta.to.shared.u64 t, %1; cvt.u32.u64 %0, t; }" : "=r"(a) : "l"(p));
    return a;
}
__device__ __forceinline__ void mma16(float (&c)[4], uint4 a, u32 b0, u32 b1) {
    asm volatile(
        "mma.sync.aligned.m16n8k16.row.col.f32.bf16.bf16.f32 "
        "{%0,%1,%2,%3},{%4,%5,%6,%7},{%8,%9},{%0,%1,%2,%3};\n"
        : "+f"(c[0]), "+f"(c[1]), "+f"(c[2]), "+f"(c[3])
        : "r"(a.x), "r"(a.y), "r"(a.z), "r"(a.w), "r"(b0), "r"(b1));
}
#define LDSM_X4(d, a) \
    asm volatile("ldmatrix.sync.aligned.m8n8.x4.shared.b16 {%0,%1,%2,%3}, [%4];" \
                 : "=r"((d).x), "=r"((d).y), "=r"((d).z), "=r"((d).w) : "r"(a))
#define LDSM_X2(d, a) \
    asm volatile("ldmatrix.sync.aligned.m8n8.x2.shared.b16 {%0,%1}, [%2];" \
                 : "=r"((d).x), "=r"((d).y) : "r"(a))
#define CP_ASYNC16(dst, src, sz) \
    asm volatile("cp.async.cg.shared.global [%0], [%1], 16, %2;" \
                 :: "r"(dst), "l"(src), "r"(sz))
#define CP_COMMIT() asm volatile("cp.async.commit_group;")
// swizzled byte offset inside a 128-row x 32B tile
__device__ __forceinline__ u32 swz(int row, int half) {
    return (u32)(row * 32 + ((half << 4) ^ ((row & 4) << 2)));
}

// ---------------- setup kernels ----------------
__global__ void init_kernel(float* __restrict__ out_ht) {
    int i = blockIdx.x * blockDim.x + threadIdx.x;
    if (i < NN * D) {
        g_c[i] = 0.0f;
        g_hhi0[i] = 0; g_hlo0[i] = 0;
        out_ht[i] = 0.0f;
    }
    if (i < NN) { g_ocnt[i] = 0; g_cnt[i] = 0; }
    if (i == 0) g_cnt[NN] = 0;
    if (i < TT * D) g_hs[i] = 0.0f;
}
__global__ void hist_kernel(const int* __restrict__ src, const int* __restrict__ dst) {
    int e = blockIdx.x * blockDim.x + threadIdx.x;
    if (e < EE) {
        atomicAdd(&g_ocnt[src[e]], 1);
        atomicAdd(&g_cnt[dst[e]], 1);
    }
}
__global__ void norm_kernel() {
    int i = blockIdx.x * blockDim.x + threadIdx.x;
    if (i < NN) {
        g_norm_src[i] = rsqrtf(fmaxf((float)g_ocnt[i], 1.0f));
        g_norm_dst[i] = rsqrtf(fmaxf((float)g_cnt[i], 1.0f));
    }
}
__global__ void scan_kernel() {
    __shared__ int ps[1024];
    const int CH = (NN + 1023) / 1024;
    int t = threadIdx.x;
    int beg = t * CH, end = min(beg + CH, NN);
    int s = 0;
    for (int i = beg; i < end; i++) s += g_cnt[i];
    ps[t] = s;
    __syncthreads();
    if (t == 0) {
        int a = 0;
        for (int i = 0; i < 1024; i++) { int v = ps[i]; ps[i] = a; a += v; }
    }
    __syncthreads();
    int off = ps[t];
    for (int i = beg; i < end; i++) {
        g_rowptr[i] = off;
        g_cursor[i] = off;
        off += g_cnt[i];
    }
    if (t == 1023) g_rowptr[NN] = off;
}
__global__ void scatter_kernel(const int* __restrict__ src, const int* __restrict__ dst) {
    int e = blockIdx.x * blockDim.x + threadIdx.x;
    if (e < EE) {
        int d = dst[e];
        int p = atomicAdd(&g_cursor[d], 1);
        g_srcsorted[p] = src[e];
    }
}
__global__ void convh_kernel(const float* __restrict__ h) {
    size_t q = (size_t)blockIdx.x * blockDim.x + threadIdx.x;
    if (q >= (size_t)NN * TT * D / 4) return;
    float4 v = ((const float4*)h)[q];
    u16 h0, h1, h2, h3, l0, l1, l2, l3;
    bsplit(v.x, h0, l0); bsplit(v.y, h1, l1);
    bsplit(v.z, h2, l2); bsplit(v.w, h3, l3);
    ((uint2*)g_xhi)[q] = make_uint2((u32)h0 | ((u32)h1 << 16), (u32)h2 | ((u32)h3 << 16));
    ((uint2*)g_xlo)[q] = make_uint2((u32)l0 | ((u32)l1 << 16), (u32)l2 | ((u32)l3 << 16));
}
// LSTM weights: row_out j*4+g <- row_in g*128+j, cols [w_ih|w_hh]
__global__ void wlprep_kernel(const float* __restrict__ w_ih, const float* __restrict__ w_hh,
                              const float* __restrict__ b_ih, const float* __restrict__ b_hh) {
    int idx = blockIdx.x * blockDim.x + threadIdx.x;
    if (idx >= 512 * 256) return;
    int ro = idx >> 8, k = idx & 255;
    int ri = (ro & 3) * D + (ro >> 2);
    float v = (k < D) ? w_ih[ri * D + k] : w_hh[ri * D + (k - D)];
    u16 hh, ll;
    bsplit(v, hh, ll);
    g_wlhi[idx] = hh; g_wllo[idx] = ll;
    if (k == 0) g_biasp[ro] = b_ih[ri] + b_hh[ri];
}
// graph weights: B[n][k] = W[k][n]
__global__ void wgprep_kernel(const float* __restrict__ Wg1, const float* __restrict__ Wg2) {
    int idx = blockIdx.x * blockDim.x + threadIdx.x;
    if (idx >= 2 * 128 * 128) return;
    int sel = idx >> 14, e = idx & 16383;
    int n = e >> 7, k = e & 127;
    float v = sel ? Wg2[k * 128 + n] : Wg1[k * 128 + n];
    u16 hh, ll;
    bsplit(v, hh, ll);
    if (sel) { g_w2hi[e] = hh; g_w2lo[e] = ll; }
    else     { g_w1hi[e] = hh; g_w1lo[e] = ll; }
}

// ---------------- SpMM: emits bf16 hi/lo pairs ----------------
__global__ __launch_bounds__(256) void spmm_kernel(const float* __restrict__ X, int ldx) {
    int w = (blockIdx.x * blockDim.x + threadIdx.x) >> 5;
    int lane = threadIdx.x & 31;
    if (w >= NN) return;
    int s0 = g_rowptr[w], s1 = g_rowptr[w + 1];
    float4 acc = make_float4(0.f, 0.f, 0.f, 0.f);
    for (int base = s0; base < s1; base += 32) {
        int n = min(32, s1 - base);
        int s = 0; float ns = 0.f;
        if (lane < n) {
            s = g_srcsorted[base + lane];
            ns = g_norm_src[s];
        }
        for (int j = 0; j < n; j++) {
            int   sj = __shfl_sync(0xffffffffu, s, j);
            float nj = __shfl_sync(0xffffffffu, ns, j);
            float4 v = *(const float4*)(X + (size_t)sj * ldx + lane * 4);
            acc.x += v.x * nj; acc.y += v.y * nj;
            acc.z += v.z * nj; acc.w += v.w * nj;
        }
    }
    float nd = g_norm_dst[w];
    u16 h0, h1, h2, h3, l0, l1, l2, l3;
    bsplit(acc.x * nd, h0, l0); bsplit(acc.y * nd, h1, l1);
    bsplit(acc.z * nd, h2, l2); bsplit(acc.w * nd, h3, l3);
    size_t q = ((size_t)w * D + lane * 4) >> 2;
    ((uint2*)g_mhi)[q] = make_uint2((u32)h0 | ((u32)h1 << 16), (u32)h2 | ((u32)h3 << 16));
    ((uint2*)g_mlo)[q] = make_uint2((u32)l0 | ((u32)l1 << 16), (u32)l2 | ((u32)l3 << 16));
}

// ==================================================================================
// bf16 3-term split GEMM, mma.m16n8k16, BM=128 BN=128 BK=16.
// cp.async double-buffered global->shared staging + ldmatrix fragment loads.
// Term-major mma issue (no accumulator RAW chains).
// MODE 0: graph conv, K=128: C = gelu(A@B^T + bias); opt C store, opt hs colsum.
// MODE 1: LSTM, K=256 (A = [x_t | h]): fused cell epilogue. grid.y = 4.
// ==================================================================================
template <int MODE>
__global__ __launch_bounds__(256, 2) void gemm_bf16(
    const u32* __restrict__ A0h, const u32* __restrict__ A0l, int ldap,   // pairs/row
    const u32* __restrict__ A1h, const u32* __restrict__ A1l,             // MODE1 h (ld 64)
    const u32* __restrict__ Bh,  const u32* __restrict__ Bl,  int ldbp,
    const float* __restrict__ bias,
    float* __restrict__ C, float* __restrict__ hsacc,
    u16* __restrict__ hoh, u16* __restrict__ hol,
    float* __restrict__ hta)
{
    __shared__ __align__(16) u32 sh[8192];   // 2 x 16KB staging buffers; epilogue reuses 32KB
    float* gtile = (float*)sh;               // epilogue [64][128]

    const int tid = threadIdx.x, lane = tid & 31;
    const int warpId = tid >> 5;
    const int warpM = warpId >> 2, warpN = warpId & 3;
    const int rowBase = blockIdx.x * 128;
    const int colBase = blockIdx.y * 128;

    const u32 smb = smem_u32(sh);

    float acc[4][4][4];
#pragma unroll
    for (int a = 0; a < 4; a++)
#pragma unroll
        for (int b = 0; b < 4; b++)
#pragma unroll
            for (int c = 0; c < 4; c++) acc[a][b][c] = 0.f;

    const int NCH = MODE ? 16 : 8;
    const int r_ = tid >> 1, half_ = tid & 1;        // staging coords
    const u32 stA = swz(r_, half_);                  // store offsets (constant over chunks)
    const int rowOK = (rowBase + r_ < NN) ? 16 : 0;
    const int rowC = (rowBase + r_ < NN) ? (rowBase + r_) : 0;   // clamped
    const int gcB = (MODE ? colBase : 0) + r_;

    // issue one chunk's cp.async set into buffer at byte offset bufoff
    auto issue_chunk = [&](int ch, u32 bufoff) {
        const u32 *ah_, *al_;
        int po, ld;
        if (MODE == 1 && ch >= 8) { ah_ = A1h; al_ = A1l; po = (ch - 8) * 8 + half_ * 4; ld = 64; }
        else                      { ah_ = A0h; al_ = A0l; po = ch * 8 + half_ * 4; ld = ldap; }
        CP_ASYNC16(smb + bufoff + stA,          ah_ + (size_t)rowC * ld + po, rowOK);
        CP_ASYNC16(smb + bufoff + 4096 + stA,   al_ + (size_t)rowC * ld + po, rowOK);
        int pb = ch * 8 + half_ * 4;
        CP_ASYNC16(smb + bufoff + 8192 + stA,   Bh + (size_t)gcB * ldbp + pb, 16);
        CP_ASYNC16(smb + bufoff + 12288 + stA,  Bl + (size_t)gcB * ldbp + pb, 16);
    };

    issue_chunk(0, 0);
    CP_COMMIT();

    for (int ch = 0; ch < NCH; ch++) {
        const u32 bufoff = (u32)((ch & 1) << 14);
        if (ch + 1 < NCH) {
            issue_chunk(ch + 1, (u32)(((ch + 1) & 1) << 14));
            CP_COMMIT();
            asm volatile("cp.async.wait_group 1;");
        } else {
            asm volatile("cp.async.wait_group 0;");
        }
        __syncthreads();
        // ---- fragment loads via ldmatrix ----
        const u32 smA_hi = smb + bufoff;
        const u32 smA_lo = smb + bufoff + 4096;
        const u32 smB_hi = smb + bufoff + 8192;
        const u32 smB_lo = smb + bufoff + 12288;
        uint4 ah[4], al[4];
        uint2 bh[4], bl[4];
        {
            int ra = lane & 15, ha = lane >> 4;
#pragma unroll
            for (int mi = 0; mi < 4; mi++) {
                int row = warpM * 64 + mi * 16 + ra;
                u32 off = swz(row, ha);
                LDSM_X4(ah[mi], smA_hi + off);
                LDSM_X4(al[mi], smA_lo + off);
            }
            int rb = lane & 7, hb = (lane >> 3) & 1;
#pragma unroll
            for (int ni = 0; ni < 4; ni++) {
                int n = warpN * 32 + ni * 8 + rb;
                u32 off = swz(n, hb);
                LDSM_X2(bh[ni], smB_hi + off);
                LDSM_X2(bl[ni], smB_lo + off);
            }
        }
        // ---- term-major mma (16 independent accs between same-acc touches) ----
#pragma unroll
        for (int ni = 0; ni < 4; ni++)
#pragma unroll
            for (int mi = 0; mi < 4; mi++)
                mma16(acc[mi][ni], ah[mi], bh[ni].x, bh[ni].y);
#pragma unroll
        for (int ni = 0; ni < 4; ni++)
#pragma unroll
            for (int mi = 0; mi < 4; mi++)
                mma16(acc[mi][ni], ah[mi], bl[ni].x, bl[ni].y);
#pragma unroll
        for (int ni = 0; ni < 4; ni++)
#pragma unroll
            for (int mi = 0; mi < 4; mi++)
                mma16(acc[mi][ni], al[mi], bh[ni].x, bh[ni].y);
        __syncthreads();
    }

    // ---- epilogue: stage through shared, 2 row-halves of 64 ----
    float csum[4] = {0.f, 0.f, 0.f, 0.f};
    const int cq = tid & 31;

    for (int half = 0; half < 2; half++) {
        __syncthreads();
        if (warpM == half) {
#pragma unroll
            for (int mi = 0; mi < 4; mi++) {
#pragma unroll
                for (int ni = 0; ni < 4; ni++) {
                    int rloc = mi * 16 + (lane >> 2);
                    int cloc = warpN * 32 + ni * 8 + (lane & 3) * 2;
                    float b0v = bias[colBase + cloc];
                    float b1v = bias[colBase + cloc + 1];
                    gtile[rloc * 128 + cloc]           = acc[mi][ni][0] + b0v;
                    gtile[rloc * 128 + cloc + 1]       = acc[mi][ni][1] + b1v;
                    gtile[(rloc + 8) * 128 + cloc]     = acc[mi][ni][2] + b0v;
                    gtile[(rloc + 8) * 128 + cloc + 1] = acc[mi][ni][3] + b1v;
                }
            }
        }
        __syncthreads();
#pragma unroll
        for (int i = 0; i < 8; i++) {
            int e = tid + i * 256;
            int rloc = e >> 5;
            int row = rowBase + half * 64 + rloc;
            if (MODE == 0) {
                float4 gv = *(const float4*)&gtile[rloc * 128 + cq * 4];
                float4 ov;
                ov.x = gelu_exact(gv.x);
                ov.y = gelu_exact(gv.y);
                ov.z = gelu_exact(gv.z);
                ov.w = gelu_exact(gv.w);
                if (row < NN) {
                    if (C != nullptr)
                        *(float4*)(C + (size_t)row * D + cq * 4) = ov;
                    csum[0] += ov.x; csum[1] += ov.y; csum[2] += ov.z; csum[3] += ov.w;
                }
            } else {
                if (row < NN) {
                    float4 gv = *(const float4*)&gtile[rloc * 128 + cq * 4];
                    int fg = blockIdx.y * 32 + cq;
                    size_t idx = (size_t)row * D + fg;
                    float cp = g_c[idx];
                    float cn = sigmoidf_(gv.y) * cp + sigmoidf_(gv.x) * tanhf(gv.z);
                    float ho = sigmoidf_(gv.w) * tanhf(cn);
                    g_c[idx] = cn;
                    hta[idx] += ho;
                    u16 hh, hl;
                    bsplit(ho, hh, hl);
                    hoh[idx] = hh;
                    hol[idx] = hl;
                }
            }
        }
    }
    if (MODE == 0 && hsacc != nullptr) {
#pragma unroll
        for (int j = 0; j < 4; j++) atomicAdd(&hsacc[cq * 4 + j], csum[j]);
    }
}

__global__ void finalize_kernel(float* __restrict__ out) {
    int idx = blockIdx.x * blockDim.x + threadIdx.x;
    if (idx < TT * D) out[idx] = g_hs[idx] * (1.0f / (float)NN);
    if (idx < NN * D) out[TT * D + idx] *= (1.0f / (float)TT);
}

// ---------------- launch ----------------
extern "C" void kernel_launch(void* const* d_in, const int* in_sizes, int n_in,
                              void* d_out, int out_size) {
    const float* h    = (const float*)d_in[0];
    const int*   src  = (const int*)d_in[1];
    const int*   dst  = (const int*)d_in[2];
    const float* Wg1  = (const float*)d_in[3];
    const float* bg1  = (const float*)d_in[4];
    const float* Wg2  = (const float*)d_in[5];
    const float* bg2  = (const float*)d_in[6];
    const float* w_ih = (const float*)d_in[7];
    const float* w_hh = (const float*)d_in[8];
    const float* b_ih = (const float*)d_in[9];
    const float* b_hh = (const float*)d_in[10];

    float* out    = (float*)d_out;
    float* out_ht = out + TT * D;

    u16 *pxhi, *pxlo, *pmhi, *pmlo, *ph0h, *ph0l, *ph1h, *ph1l;
    u16 *pwlh, *pwll, *pw1h, *pw1l, *pw2h, *pw2l;
    float *pxact, *pbp, *phs;
    cudaGetSymbolAddress((void**)&pxhi, g_xhi);
    cudaGetSymbolAddress((void**)&pxlo, g_xlo);
    cudaGetSymbolAddress((void**)&pmhi, g_mhi);
    cudaGetSymbolAddress((void**)&pmlo, g_mlo);
    cudaGetSymbolAddress((void**)&ph0h, g_hhi0);
    cudaGetSymbolAddress((void**)&ph0l, g_hlo0);
    cudaGetSymbolAddress((void**)&ph1h, g_hhi1);
    cudaGetSymbolAddress((void**)&ph1l, g_hlo1);
    cudaGetSymbolAddress((void**)&pwlh, g_wlhi);
    cudaGetSymbolAddress((void**)&pwll, g_wllo);
    cudaGetSymbolAddress((void**)&pw1h, g_w1hi);
    cudaGetSymbolAddress((void**)&pw1l, g_w1lo);
    cudaGetSymbolAddress((void**)&pw2h, g_w2hi);
    cudaGetSymbolAddress((void**)&pw2l, g_w2lo);
    cudaGetSymbolAddress((void**)&pxact, g_xact);
    cudaGetSymbolAddress((void**)&pbp, g_biasp);
    cudaGetSymbolAddress((void**)&phs, g_hs);

    // fork/join resources (host objects only)
    cudaStream_t s2;
    cudaStreamCreateWithFlags(&s2, cudaStreamNonBlocking);
    cudaEvent_t e1, e2;
    cudaEventCreateWithFlags(&e1, cudaEventDisableTiming);
    cudaEventCreateWithFlags(&e2, cudaEventDisableTiming);

    // common setup on main stream
    init_kernel<<<(NN * D + 255) / 256, 256>>>(out_ht);
    wlprep_kernel<<<(512 * 256 + 255) / 256, 256>>>(w_ih, w_hh, b_ih, b_hh);
    convh_kernel<<<(int)(((size_t)NN * TT * D / 4 + 255) / 256), 256>>>(h);

    // fork: LSTM chain on s2
    cudaEventRecord(e1, 0);
    cudaStreamWaitEvent(s2, e1, 0);

    const int gx = (NN + 127) / 128;   // 391
    u16 *hih = ph0h, *hil = ph0l, *hoh = ph1h, *hol = ph1l;
    for (int t = 0; t < TT; t++) {
        gemm_bf16<1><<<dim3(gx, 4), 256, 0, s2>>>(
            (u32*)pxhi + (size_t)t * 64, (u32*)pxlo + (size_t)t * 64, TT * 64,
            (u32*)hih, (u32*)hil,
            (u32*)pwlh, (u32*)pwll, 128, pbp,
            nullptr, nullptr, hoh, hol, out_ht);
        u16* t1 = hih; hih = hoh; hoh = t1;
        u16* t2 = hil; hil = hol; hol = t2;
    }
    cudaEventRecord(e2, s2);

    // graph chain on main stream
    hist_kernel<<<(EE + 255) / 256, 256>>>(src, dst);
    norm_kernel<<<(NN + 255) / 256, 256>>>();
    wgprep_kernel<<<(2 * 128 * 128 + 255) / 256, 256>>>(Wg1, Wg2);
    scan_kernel<<<1, 1024>>>();
    scatter_kernel<<<(EE + 255) / 256, 256>>>(src, dst);

    int spmm_blocks = (NN * 32 + 255) / 256;
    for (int t = 0; t < TT; t++) {
        spmm_kernel<<<spmm_blocks, 256>>>(h + t * D, TT * D);
        gemm_bf16<0><<<dim3(gx, 1), 256>>>((u32*)pmhi, (u32*)pmlo, 64, nullptr, nullptr,
                                           (u32*)pw1h, (u32*)pw1l, 64, bg1,
                                           pxact, nullptr, nullptr, nullptr, nullptr);
        spmm_kernel<<<spmm_blocks, 256>>>(pxact, D);
        gemm_bf16<0><<<dim3(gx, 1), 256>>>((u32*)pmhi, (u32*)pmlo, 64, nullptr, nullptr,
                                           (u32*)pw2h, (u32*)pw2l, 64, bg2,
                                           nullptr, phs + t * D, nullptr, nullptr, nullptr);
    }

    // join and finalize
    cudaStreamWaitEvent(0, e2, 0);
    finalize_kernel<<<(NN * D + 255) / 256, 256>>>(out);
}

// round 13
// speedup vs baseline: 1.5727x; 1.1040x over previous
#include <cuda_runtime.h>
#include <cuda_fp16.h>
#include <math.h>
#include <stdint.h>

#define NN 50000
#define EE 800000
#define TT 12
#define D  128

typedef unsigned short u16;
typedef unsigned int   u32;

// ---------------- scratch ----------------
__device__ float g_norm_src[NN], g_norm_dst[NN];
__device__ int g_ocnt[NN], g_cnt[NN + 1], g_rowptr[NN + 1], g_cursor[NN];
__device__ int g_srcsorted[EE];
__device__ __align__(16) u16 g_xhi[(size_t)NN * TT * D];   // x fp16 hi (pair-packed along k)
__device__ __align__(16) u16 g_xlo[(size_t)NN * TT * D];   // x fp16 lo
__device__ __align__(16) u16 g_mhi[(size_t)NN * D];        // spmm out fp16 hi
__device__ __align__(16) u16 g_mlo[(size_t)NN * D];
__device__ __align__(16) float g_xact[(size_t)NN * D];     // layer-1 act (fp32, spmm2 input)
__device__ __align__(16) u16 g_hhi0[(size_t)NN * D], g_hlo0[(size_t)NN * D];
__device__ __align__(16) u16 g_hhi1[(size_t)NN * D], g_hlo1[(size_t)NN * D];
__device__ __align__(16) float g_c[(size_t)NN * D];
__device__ __align__(16) u16 g_wlh[512 * 256];             // [n][k] fp16, quad-permuted rows
__device__ __align__(16) u16 g_w1h[128 * 128];             // [n][k] fp16
__device__ __align__(16) u16 g_w2h[128 * 128];
__device__ float g_biasp[512];
__device__ float g_hs[TT * D];

// ---------------- helpers ----------------
__device__ __forceinline__ float gelu_exact(float v) {
    return 0.5f * v * (1.0f + erff(v * 0.70710678118654752f));
}
__device__ __forceinline__ float sigmoidf_(float v) {
    return 1.0f / (1.0f + __expf(-v));
}
// fp16 hi/lo split: hi = rn(x), lo = rn(x - hi); dropped residual ~2^-22 rel
__device__ __forceinline__ void hsplit(float x, u16& h, u16& l) {
    __half hh = __float2half_rn(x);
    float hr = __half2float(hh);
    __half ll = __float2half_rn(x - hr);
    h = *(u16*)&hh;
    l = *(u16*)&ll;
}
__device__ __forceinline__ u16 h1(float x) {
    __half hh = __float2half_rn(x);
    return *(u16*)&hh;
}
__device__ __forceinline__ u32 smem_u32(const void* p) {
    u32 a;
    asm("{ .reg .u64 t; cvta.to.shared.u64 t, %1; cvt.u32.u64 %0, t; }" : "=r"(a) : "l"(p));
    return a;
}
__device__ __forceinline__ void mma16(float (&c)[4], uint4 a, u32 b0, u32 b1) {
    asm volatile(
        "mma.sync.aligned.m16n8k16.row.col.f32.f16.f16.f32 "
        "{%0,%1,%2,%3},{%4,%5,%6,%7},{%8,%9},{%0,%1,%2,%3};\n"
        : "+f"(c[0]), "+f"(c[1]), "+f"(c[2]), "+f"(c[3])
        : "r"(a.x), "r"(a.y), "r"(a.z), "r"(a.w), "r"(b0), "r"(b1));
}
#define LDSM_X4(d, a) \
    asm volatile("ldmatrix.sync.aligned.m8n8.x4.shared.b16 {%0,%1,%2,%3}, [%4];" \
                 : "=r"((d).x), "=r"((d).y), "=r"((d).z), "=r"((d).w) : "r"(a))
#define LDSM_X2(d, a) \
    asm volatile("ldmatrix.sync.aligned.m8n8.x2.shared.b16 {%0,%1}, [%2];" \
                 : "=r"((d).x), "=r"((d).y) : "r"(a))
#define CP_ASYNC16(dst, src, sz) \
    asm volatile("cp.async.cg.shared.global [%0], [%1], 16, %2;" \
                 :: "r"(dst), "l"(src), "r"(sz))
#define CP_COMMIT() asm volatile("cp.async.commit_group;")
// swizzled byte offset inside a 128-row x 32B tile
__device__ __forceinline__ u32 swz(int row, int half) {
    return (u32)(row * 32 + ((half << 4) ^ ((row & 4) << 2)));
}

// ---------------- setup kernels ----------------
__global__ void init_kernel(float* __restrict__ out_ht) {
    int i = blockIdx.x * blockDim.x + threadIdx.x;
    if (i < NN * D) {
        g_c[i] = 0.0f;
        g_hhi0[i] = 0; g_hlo0[i] = 0;
        out_ht[i] = 0.0f;
    }
    if (i < NN) { g_ocnt[i] = 0; g_cnt[i] = 0; }
    if (i == 0) g_cnt[NN] = 0;
    if (i < TT * D) g_hs[i] = 0.0f;
}
__global__ void hist_kernel(const int* __restrict__ src, const int* __restrict__ dst) {
    int e = blockIdx.x * blockDim.x + threadIdx.x;
    if (e < EE) {
        atomicAdd(&g_ocnt[src[e]], 1);
        atomicAdd(&g_cnt[dst[e]], 1);
    }
}
__global__ void norm_kernel() {
    int i = blockIdx.x * blockDim.x + threadIdx.x;
    if (i < NN) {
        g_norm_src[i] = rsqrtf(fmaxf((float)g_ocnt[i], 1.0f));
        g_norm_dst[i] = rsqrtf(fmaxf((float)g_cnt[i], 1.0f));
    }
}
__global__ void scan_kernel() {
    __shared__ int ps[1024];
    const int CH = (NN + 1023) / 1024;
    int t = threadIdx.x;
    int beg = t * CH, end = min(beg + CH, NN);
    int s = 0;
    for (int i = beg; i < end; i++) s += g_cnt[i];
    ps[t] = s;
    __syncthreads();
    if (t == 0) {
        int a = 0;
        for (int i = 0; i < 1024; i++) { int v = ps[i]; ps[i] = a; a += v; }
    }
    __syncthreads();
    int off = ps[t];
    for (int i = beg; i < end; i++) {
        g_rowptr[i] = off;
        g_cursor[i] = off;
        off += g_cnt[i];
    }
    if (t == 1023) g_rowptr[NN] = off;
}
__global__ void scatter_kernel(const int* __restrict__ src, const int* __restrict__ dst) {
    int e = blockIdx.x * blockDim.x + threadIdx.x;
    if (e < EE) {
        int d = dst[e];
        int p = atomicAdd(&g_cursor[d], 1);
        g_srcsorted[p] = src[e];
    }
}
__global__ void convh_kernel(const float* __restrict__ h) {
    size_t q = (size_t)blockIdx.x * blockDim.x + threadIdx.x;
    if (q >= (size_t)NN * TT * D / 4) return;
    float4 v = ((const float4*)h)[q];
    u16 h0, h1_, h2, h3, l0, l1, l2, l3;
    hsplit(v.x, h0, l0); hsplit(v.y, h1_, l1);
    hsplit(v.z, h2, l2); hsplit(v.w, h3, l3);
    ((uint2*)g_xhi)[q] = make_uint2((u32)h0 | ((u32)h1_ << 16), (u32)h2 | ((u32)h3 << 16));
    ((uint2*)g_xlo)[q] = make_uint2((u32)l0 | ((u32)l1 << 16), (u32)l2 | ((u32)l3 << 16));
}
// LSTM weights: row_out j*4+g <- row_in g*128+j, cols [w_ih|w_hh]; single fp16
__global__ void wlprep_kernel(const float* __restrict__ w_ih, const float* __restrict__ w_hh,
                              const float* __restrict__ b_ih, const float* __restrict__ b_hh) {
    int idx = blockIdx.x * blockDim.x + threadIdx.x;
    if (idx >= 512 * 256) return;
    int ro = idx >> 8, k = idx & 255;
    int ri = (ro & 3) * D + (ro >> 2);
    float v = (k < D) ? w_ih[ri * D + k] : w_hh[ri * D + (k - D)];
    g_wlh[idx] = h1(v);
    if (k == 0) g_biasp[ro] = b_ih[ri] + b_hh[ri];
}
// graph weights: B[n][k] = W[k][n]; single fp16
__global__ void wgprep_kernel(const float* __restrict__ Wg1, const float* __restrict__ Wg2) {
    int idx = blockIdx.x * blockDim.x + threadIdx.x;
    if (idx >= 2 * 128 * 128) return;
    int sel = idx >> 14, e = idx & 16383;
    int n = e >> 7, k = e & 127;
    float v = sel ? Wg2[k * 128 + n] : Wg1[k * 128 + n];
    if (sel) g_w2h[e] = h1(v);
    else     g_w1h[e] = h1(v);
}

// ---------------- SpMM: emits fp16 hi/lo pairs ----------------
__global__ __launch_bounds__(256) void spmm_kernel(const float* __restrict__ X, int ldx) {
    int w = (blockIdx.x * blockDim.x + threadIdx.x) >> 5;
    int lane = threadIdx.x & 31;
    if (w >= NN) return;
    int s0 = g_rowptr[w], s1 = g_rowptr[w + 1];
    float4 acc = make_float4(0.f, 0.f, 0.f, 0.f);
    for (int base = s0; base < s1; base += 32) {
        int n = min(32, s1 - base);
        int s = 0; float ns = 0.f;
        if (lane < n) {
            s = g_srcsorted[base + lane];
            ns = g_norm_src[s];
        }
        for (int j = 0; j < n; j++) {
            int   sj = __shfl_sync(0xffffffffu, s, j);
            float nj = __shfl_sync(0xffffffffu, ns, j);
            float4 v = *(const float4*)(X + (size_t)sj * ldx + lane * 4);
            acc.x += v.x * nj; acc.y += v.y * nj;
            acc.z += v.z * nj; acc.w += v.w * nj;
        }
    }
    float nd = g_norm_dst[w];
    u16 h0, h1_, h2, h3, l0, l1, l2, l3;
    hsplit(acc.x * nd, h0, l0); hsplit(acc.y * nd, h1_, l1);
    hsplit(acc.z * nd, h2, l2); hsplit(acc.w * nd, h3, l3);
    size_t q = ((size_t)w * D + lane * 4) >> 2;
    ((uint2*)g_mhi)[q] = make_uint2((u32)h0 | ((u32)h1_ << 16), (u32)h2 | ((u32)h3 << 16));
    ((uint2*)g_mlo)[q] = make_uint2((u32)l0 | ((u32)l1 << 16), (u32)l2 | ((u32)l3 << 16));
}

// ==================================================================================
// fp16 2-term split GEMM (A = Ahi+Alo fp16, B single fp16), mma.m16n8k16.
// BM=128 BN=128 BK=16, cp.async double-buffered staging + ldmatrix, term-major mma.
// MODE 0: graph conv, K=128: C = gelu(A@B^T + bias); opt C store, opt hs colsum.
// MODE 1: LSTM, K=256 (A = [x_t | h]): fused cell epilogue. grid.y = 4.
// ==================================================================================
template <int MODE>
__global__ __launch_bounds__(256, 2) void gemm_f16(
    const u32* __restrict__ A0h, const u32* __restrict__ A0l, int ldap,   // pairs/row
    const u32* __restrict__ A1h, const u32* __restrict__ A1l,             // MODE1 h (ld 64)
    const u32* __restrict__ Bh,  int ldbp,
    const float* __restrict__ bias,
    float* __restrict__ C, float* __restrict__ hsacc,
    u16* __restrict__ hoh, u16* __restrict__ hol,
    float* __restrict__ hta)
{
    __shared__ __align__(16) u32 sh[8192];   // 2 x 12KB staging; epilogue reuses 32KB
    float* gtile = (float*)sh;               // epilogue [64][128]

    const int tid = threadIdx.x, lane = tid & 31;
    const int warpId = tid >> 5;
    const int warpM = warpId >> 2, warpN = warpId & 3;
    const int rowBase = blockIdx.x * 128;
    const int colBase = blockIdx.y * 128;

    const u32 smb = smem_u32(sh);

    float acc[4][4][4];
#pragma unroll
    for (int a = 0; a < 4; a++)
#pragma unroll
        for (int b = 0; b < 4; b++)
#pragma unroll
            for (int c = 0; c < 4; c++) acc[a][b][c] = 0.f;

    const int NCH = MODE ? 16 : 8;
    const int r_ = tid >> 1, half_ = tid & 1;        // staging coords
    const u32 stA = swz(r_, half_);                  // store offsets (constant over chunks)
    const int rowOK = (rowBase + r_ < NN) ? 16 : 0;
    const int rowC = (rowBase + r_ < NN) ? (rowBase + r_) : 0;   // clamped
    const int gcB = (MODE ? colBase : 0) + r_;

    // buffer layout: Ahi[0,4096) Alo[4096,8192) B[8192,12288); stride 12288
    auto issue_chunk = [&](int ch, u32 bufoff) {
        const u32 *ah_, *al_;
        int po, ld;
        if (MODE == 1 && ch >= 8) { ah_ = A1h; al_ = A1l; po = (ch - 8) * 8 + half_ * 4; ld = 64; }
        else                      { ah_ = A0h; al_ = A0l; po = ch * 8 + half_ * 4; ld = ldap; }
        CP_ASYNC16(smb + bufoff + stA,         ah_ + (size_t)rowC * ld + po, rowOK);
        CP_ASYNC16(smb + bufoff + 4096 + stA,  al_ + (size_t)rowC * ld + po, rowOK);
        int pb = ch * 8 + half_ * 4;
        CP_ASYNC16(smb + bufoff + 8192 + stA,  Bh + (size_t)gcB * ldbp + pb, 16);
    };

    issue_chunk(0, 0);
    CP_COMMIT();

    for (int ch = 0; ch < NCH; ch++) {
        const u32 bufoff = (u32)((ch & 1) * 12288);
        if (ch + 1 < NCH) {
            issue_chunk(ch + 1, (u32)(((ch + 1) & 1) * 12288));
            CP_COMMIT();
            asm volatile("cp.async.wait_group 1;");
        } else {
            asm volatile("cp.async.wait_group 0;");
        }
        __syncthreads();
        // ---- fragment loads via ldmatrix ----
        const u32 smA_hi = smb + bufoff;
        const u32 smA_lo = smb + bufoff + 4096;
        const u32 smB   = smb + bufoff + 8192;
        uint4 ah[4], al[4];
        uint2 bb[4];
        {
            int ra = lane & 15, ha = lane >> 4;
#pragma unroll
            for (int mi = 0; mi < 4; mi++) {
                int row = warpM * 64 + mi * 16 + ra;
                u32 off = swz(row, ha);
                LDSM_X4(ah[mi], smA_hi + off);
                LDSM_X4(al[mi], smA_lo + off);
            }
            int rb = lane & 7, hb = (lane >> 3) & 1;
#pragma unroll
            for (int ni = 0; ni < 4; ni++) {
                int n = warpN * 32 + ni * 8 + rb;
                u32 off = swz(n, hb);
                LDSM_X2(bb[ni], smB + off);
            }
        }
        // ---- term-major mma (16 independent accs between same-acc touches) ----
#pragma unroll
        for (int ni = 0; ni < 4; ni++)
#pragma unroll
            for (int mi = 0; mi < 4; mi++)
                mma16(acc[mi][ni], ah[mi], bb[ni].x, bb[ni].y);
#pragma unroll
        for (int ni = 0; ni < 4; ni++)
#pragma unroll
            for (int mi = 0; mi < 4; mi++)
                mma16(acc[mi][ni], al[mi], bb[ni].x, bb[ni].y);
        __syncthreads();
    }

    // ---- epilogue: stage through shared, 2 row-halves of 64 ----
    float csum[4] = {0.f, 0.f, 0.f, 0.f};
    const int cq = tid & 31;

    for (int half = 0; half < 2; half++) {
        __syncthreads();
        if (warpM == half) {
#pragma unroll
            for (int mi = 0; mi < 4; mi++) {
#pragma unroll
                for (int ni = 0; ni < 4; ni++) {
                    int rloc = mi * 16 + (lane >> 2);
                    int cloc = warpN * 32 + ni * 8 + (lane & 3) * 2;
                    float b0v = bias[colBase + cloc];
                    float b1v = bias[colBase + cloc + 1];
                    gtile[rloc * 128 + cloc]           = acc[mi][ni][0] + b0v;
                    gtile[rloc * 128 + cloc + 1]       = acc[mi][ni][1] + b1v;
                    gtile[(rloc + 8) * 128 + cloc]     = acc[mi][ni][2] + b0v;
                    gtile[(rloc + 8) * 128 + cloc + 1] = acc[mi][ni][3] + b1v;
                }
            }
        }
        __syncthreads();
#pragma unroll
        for (int i = 0; i < 8; i++) {
            int e = tid + i * 256;
            int rloc = e >> 5;
            int row = rowBase + half * 64 + rloc;
            if (MODE == 0) {
                float4 gv = *(const float4*)&gtile[rloc * 128 + cq * 4];
                float4 ov;
                ov.x = gelu_exact(gv.x);
                ov.y = gelu_exact(gv.y);
                ov.z = gelu_exact(gv.z);
                ov.w = gelu_exact(gv.w);
                if (row < NN) {
                    if (C != nullptr)
                        *(float4*)(C + (size_t)row * D + cq * 4) = ov;
                    csum[0] += ov.x; csum[1] += ov.y; csum[2] += ov.z; csum[3] += ov.w;
                }
            } else {
                if (row < NN) {
                    float4 gv = *(const float4*)&gtile[rloc * 128 + cq * 4];
                    int fg = blockIdx.y * 32 + cq;
                    size_t idx = (size_t)row * D + fg;
                    float cp = g_c[idx];
                    float cn = sigmoidf_(gv.y) * cp + sigmoidf_(gv.x) * tanhf(gv.z);
                    float ho = sigmoidf_(gv.w) * tanhf(cn);
                    g_c[idx] = cn;
                    hta[idx] += ho;
                    u16 hh, hl;
                    hsplit(ho, hh, hl);
                    hoh[idx] = hh;
                    hol[idx] = hl;
                }
            }
        }
    }
    if (MODE == 0 && hsacc != nullptr) {
#pragma unroll
        for (int j = 0; j < 4; j++) atomicAdd(&hsacc[cq * 4 + j], csum[j]);
    }
}

__global__ void finalize_kernel(float* __restrict__ out) {
    int idx = blockIdx.x * blockDim.x + threadIdx.x;
    if (idx < TT * D) out[idx] = g_hs[idx] * (1.0f / (float)NN);
    if (idx < NN * D) out[TT * D + idx] *= (1.0f / (float)TT);
}

// ---------------- launch ----------------
extern "C" void kernel_launch(void* const* d_in, const int* in_sizes, int n_in,
                              void* d_out, int out_size) {
    const float* h    = (const float*)d_in[0];
    const int*   src  = (const int*)d_in[1];
    const int*   dst  = (const int*)d_in[2];
    const float* Wg1  = (const float*)d_in[3];
    const float* bg1  = (const float*)d_in[4];
    const float* Wg2  = (const float*)d_in[5];
    const float* bg2  = (const float*)d_in[6];
    const float* w_ih = (const float*)d_in[7];
    const float* w_hh = (const float*)d_in[8];
    const float* b_ih = (const float*)d_in[9];
    const float* b_hh = (const float*)d_in[10];

    float* out    = (float*)d_out;
    float* out_ht = out + TT * D;

    u16 *pxhi, *pxlo, *pmhi, *pmlo, *ph0h, *ph0l, *ph1h, *ph1l;
    u16 *pwlh, *pw1h, *pw2h;
    float *pxact, *pbp, *phs;
    cudaGetSymbolAddress((void**)&pxhi, g_xhi);
    cudaGetSymbolAddress((void**)&pxlo, g_xlo);
    cudaGetSymbolAddress((void**)&pmhi, g_mhi);
    cudaGetSymbolAddress((void**)&pmlo, g_mlo);
    cudaGetSymbolAddress((void**)&ph0h, g_hhi0);
    cudaGetSymbolAddress((void**)&ph0l, g_hlo0);
    cudaGetSymbolAddress((void**)&ph1h, g_hhi1);
    cudaGetSymbolAddress((void**)&ph1l, g_hlo1);
    cudaGetSymbolAddress((void**)&pwlh, g_wlh);
    cudaGetSymbolAddress((void**)&pw1h, g_w1h);
    cudaGetSymbolAddress((void**)&pw2h, g_w2h);
    cudaGetSymbolAddress((void**)&pxact, g_xact);
    cudaGetSymbolAddress((void**)&pbp, g_biasp);
    cudaGetSymbolAddress((void**)&phs, g_hs);

    // fork/join resources (host objects only)
    cudaStream_t s2;
    cudaStreamCreateWithFlags(&s2, cudaStreamNonBlocking);
    cudaEvent_t e1, e2;
    cudaEventCreateWithFlags(&e1, cudaEventDisableTiming);
    cudaEventCreateWithFlags(&e2, cudaEventDisableTiming);

    // common setup on main stream
    init_kernel<<<(NN * D + 255) / 256, 256>>>(out_ht);
    wlprep_kernel<<<(512 * 256 + 255) / 256, 256>>>(w_ih, w_hh, b_ih, b_hh);
    convh_kernel<<<(int)(((size_t)NN * TT * D / 4 + 255) / 256), 256>>>(h);

    // fork: LSTM chain on s2
    cudaEventRecord(e1, 0);
    cudaStreamWaitEvent(s2, e1, 0);

    const int gx = (NN + 127) / 128;   // 391
    u16 *hih = ph0h, *hil = ph0l, *hoh = ph1h, *hol = ph1l;
    for (int t = 0; t < TT; t++) {
        gemm_f16<1><<<dim3(gx, 4), 256, 0, s2>>>(
            (u32*)pxhi + (size_t)t * 64, (u32*)pxlo + (size_t)t * 64, TT * 64,
            (u32*)hih, (u32*)hil,
            (u32*)pwlh, 128, pbp,
            nullptr, nullptr, hoh, hol, out_ht);
        u16* t1 = hih; hih = hoh; hoh = t1;
        u16* t2 = hil; hil = hol; hol = t2;
    }
    cudaEventRecord(e2, s2);

    // graph chain on main stream
    hist_kernel<<<(EE + 255) / 256, 256>>>(src, dst);
    norm_kernel<<<(NN + 255) / 256, 256>>>();
    wgprep_kernel<<<(2 * 128 * 128 + 255) / 256, 256>>>(Wg1, Wg2);
    scan_kernel<<<1, 1024>>>();
    scatter_kernel<<<(EE + 255) / 256, 256>>>(src, dst);

    int spmm_blocks = (NN * 32 + 255) / 256;
    for (int t = 0; t < TT; t++) {
        spmm_kernel<<<spmm_blocks, 256>>>(h + t * D, TT * D);
        gemm_f16<0><<<dim3(gx, 1), 256>>>((u32*)pmhi, (u32*)pmlo, 64, nullptr, nullptr,
                                          (u32*)pw1h, 64, bg1,
                                          pxact, nullptr, nullptr, nullptr, nullptr);
        spmm_kernel<<<spmm_blocks, 256>>>(pxact, D);
        gemm_f16<0><<<dim3(gx, 1), 256>>>((u32*)pmhi, (u32*)pmlo, 64, nullptr, nullptr,
                                          (u32*)pw2h, 64, bg2,
                                          nullptr, phs + t * D, nullptr, nullptr, nullptr);
    }

    // join and finalize
    cudaStreamWaitEvent(0, e2, 0);
    finalize_kernel<<<(NN * D + 255) / 256, 256>>>(out);
}

// round 14
// speedup vs baseline: 1.8385x; 1.1690x over previous
#include <cuda_runtime.h>
#include <cuda_fp16.h>
#include <math.h>
#include <stdint.h>

#define NN 50000
#define EE 800000
#define TT 12
#define D  128

typedef unsigned short u16;
typedef unsigned int   u32;

// ---------------- scratch ----------------
__device__ float g_norm_src[NN], g_norm_dst[NN];
__device__ int g_ocnt[NN], g_cnt[NN + 1], g_rowptr[NN + 1], g_cursor[NN];
__device__ int g_srcsorted[EE];
__device__ __align__(16) u16 g_xh[(size_t)NN * TT * D];    // x fp16 (pair-packed along k)
__device__ __align__(16) u16 g_mh[(size_t)NN * D];         // spmm out fp16
__device__ __align__(16) float g_xact[(size_t)NN * D];     // layer-1 act (fp32, spmm2 input)
__device__ __align__(16) u16 g_h0[(size_t)NN * D], g_h1[(size_t)NN * D];  // LSTM h fp16
__device__ __align__(16) float g_c[(size_t)NN * D];
__device__ __align__(16) u16 g_wlh[512 * 256];             // [n][k] fp16, quad-permuted rows
__device__ __align__(16) u16 g_w1h[128 * 128];             // [n][k] fp16
__device__ __align__(16) u16 g_w2h[128 * 128];
__device__ float g_biasp[512];
__device__ float g_hs[TT * D];

// ---------------- helpers ----------------
__device__ __forceinline__ float gelu_exact(float v) {
    return 0.5f * v * (1.0f + erff(v * 0.70710678118654752f));
}
__device__ __forceinline__ float sigmoidf_(float v) {
    return 1.0f / (1.0f + __expf(-v));
}
__device__ __forceinline__ u16 h1(float x) {
    __half hh = __float2half_rn(x);
    return *(u16*)&hh;
}
__device__ __forceinline__ u32 smem_u32(const void* p) {
    u32 a;
    asm("{ .reg .u64 t; cvta.to.shared.u64 t, %1; cvt.u32.u64 %0, t; }" : "=r"(a) : "l"(p));
    return a;
}
__device__ __forceinline__ void mma16(float (&c)[4], uint4 a, u32 b0, u32 b1) {
    asm volatile(
        "mma.sync.aligned.m16n8k16.row.col.f32.f16.f16.f32 "
        "{%0,%1,%2,%3},{%4,%5,%6,%7},{%8,%9},{%0,%1,%2,%3};\n"
        : "+f"(c[0]), "+f"(c[1]), "+f"(c[2]), "+f"(c[3])
        : "r"(a.x), "r"(a.y), "r"(a.z), "r"(a.w), "r"(b0), "r"(b1));
}
#define LDSM_X4(d, a) \
    asm volatile("ldmatrix.sync.aligned.m8n8.x4.shared.b16 {%0,%1,%2,%3}, [%4];" \
                 : "=r"((d).x), "=r"((d).y), "=r"((d).z), "=r"((d).w) : "r"(a))
#define LDSM_X2(d, a) \
    asm volatile("ldmatrix.sync.aligned.m8n8.x2.shared.b16 {%0,%1}, [%2];" \
                 : "=r"((d).x), "=r"((d).y) : "r"(a))
#define CP_ASYNC16(dst, src, sz) \
    asm volatile("cp.async.cg.shared.global [%0], [%1], 16, %2;" \
                 :: "r"(dst), "l"(src), "r"(sz))
#define CP_COMMIT() asm volatile("cp.async.commit_group;")
// swizzled byte offset inside a 128-row x 32B tile
__device__ __forceinline__ u32 swz(int row, int half) {
    return (u32)(row * 32 + ((half << 4) ^ ((row & 4) << 2)));
}

// ---------------- setup kernels ----------------
__global__ void init_kernel(float* __restrict__ out_ht) {
    int i = blockIdx.x * blockDim.x + threadIdx.x;
    if (i < NN * D) {
        g_c[i] = 0.0f;
        g_h0[i] = 0;
        out_ht[i] = 0.0f;
    }
    if (i < NN) { g_ocnt[i] = 0; g_cnt[i] = 0; }
    if (i == 0) g_cnt[NN] = 0;
    if (i < TT * D) g_hs[i] = 0.0f;
}
__global__ void hist_kernel(const int* __restrict__ src, const int* __restrict__ dst) {
    int e = blockIdx.x * blockDim.x + threadIdx.x;
    if (e < EE) {
        atomicAdd(&g_ocnt[src[e]], 1);
        atomicAdd(&g_cnt[dst[e]], 1);
    }
}
__global__ void norm_kernel() {
    int i = blockIdx.x * blockDim.x + threadIdx.x;
    if (i < NN) {
        g_norm_src[i] = rsqrtf(fmaxf((float)g_ocnt[i], 1.0f));
        g_norm_dst[i] = rsqrtf(fmaxf((float)g_cnt[i], 1.0f));
    }
}
__global__ void scan_kernel() {
    __shared__ int ps[1024];
    const int CH = (NN + 1023) / 1024;
    int t = threadIdx.x;
    int beg = t * CH, end = min(beg + CH, NN);
    int s = 0;
    for (int i = beg; i < end; i++) s += g_cnt[i];
    ps[t] = s;
    __syncthreads();
    if (t == 0) {
        int a = 0;
        for (int i = 0; i < 1024; i++) { int v = ps[i]; ps[i] = a; a += v; }
    }
    __syncthreads();
    int off = ps[t];
    for (int i = beg; i < end; i++) {
        g_rowptr[i] = off;
        g_cursor[i] = off;
        off += g_cnt[i];
    }
    if (t == 1023) g_rowptr[NN] = off;
}
__global__ void scatter_kernel(const int* __restrict__ src, const int* __restrict__ dst) {
    int e = blockIdx.x * blockDim.x + threadIdx.x;
    if (e < EE) {
        int d = dst[e];
        int p = atomicAdd(&g_cursor[d], 1);
        g_srcsorted[p] = src[e];
    }
}
__global__ void convh_kernel(const float* __restrict__ h) {
    size_t q = (size_t)blockIdx.x * blockDim.x + threadIdx.x;
    if (q >= (size_t)NN * TT * D / 4) return;
    float4 v = ((const float4*)h)[q];
    ((uint2*)g_xh)[q] = make_uint2((u32)h1(v.x) | ((u32)h1(v.y) << 16),
                                   (u32)h1(v.z) | ((u32)h1(v.w) << 16));
}
// LSTM weights: row_out j*4+g <- row_in g*128+j, cols [w_ih|w_hh]; fp16
__global__ void wlprep_kernel(const float* __restrict__ w_ih, const float* __restrict__ w_hh,
                              const float* __restrict__ b_ih, const float* __restrict__ b_hh) {
    int idx = blockIdx.x * blockDim.x + threadIdx.x;
    if (idx >= 512 * 256) return;
    int ro = idx >> 8, k = idx & 255;
    int ri = (ro & 3) * D + (ro >> 2);
    float v = (k < D) ? w_ih[ri * D + k] : w_hh[ri * D + (k - D)];
    g_wlh[idx] = h1(v);
    if (k == 0) g_biasp[ro] = b_ih[ri] + b_hh[ri];
}
// graph weights: B[n][k] = W[k][n]; fp16
__global__ void wgprep_kernel(const float* __restrict__ Wg1, const float* __restrict__ Wg2) {
    int idx = blockIdx.x * blockDim.x + threadIdx.x;
    if (idx >= 2 * 128 * 128) return;
    int sel = idx >> 14, e = idx & 16383;
    int n = e >> 7, k = e & 127;
    float v = sel ? Wg2[k * 128 + n] : Wg1[k * 128 + n];
    if (sel) g_w2h[e] = h1(v);
    else     g_w1h[e] = h1(v);
}

// ---------------- SpMM: emits fp16 ----------------
__global__ __launch_bounds__(256) void spmm_kernel(const float* __restrict__ X, int ldx) {
    int w = (blockIdx.x * blockDim.x + threadIdx.x) >> 5;
    int lane = threadIdx.x & 31;
    if (w >= NN) return;
    int s0 = g_rowptr[w], s1 = g_rowptr[w + 1];
    float4 acc = make_float4(0.f, 0.f, 0.f, 0.f);
    for (int base = s0; base < s1; base += 32) {
        int n = min(32, s1 - base);
        int s = 0; float ns = 0.f;
        if (lane < n) {
            s = g_srcsorted[base + lane];
            ns = g_norm_src[s];
        }
        for (int j = 0; j < n; j++) {
            int   sj = __shfl_sync(0xffffffffu, s, j);
            float nj = __shfl_sync(0xffffffffu, ns, j);
            float4 v = *(const float4*)(X + (size_t)sj * ldx + lane * 4);
            acc.x += v.x * nj; acc.y += v.y * nj;
            acc.z += v.z * nj; acc.w += v.w * nj;
        }
    }
    float nd = g_norm_dst[w];
    size_t q = ((size_t)w * D + lane * 4) >> 2;
    ((uint2*)g_mh)[q] = make_uint2((u32)h1(acc.x * nd) | ((u32)h1(acc.y * nd) << 16),
                                   (u32)h1(acc.z * nd) | ((u32)h1(acc.w * nd) << 16));
}

// ==================================================================================
// fp16 GEMM, mma.m16n8k16, BM=128 BN=128 BK=16.
// 3-stage cp.async pipeline, ONE __syncthreads per chunk, ldmatrix, term-major mma.
// MODE 0: graph conv, K=128: C = gelu(A@B^T + bias); opt C store, opt hs colsum.
// MODE 1: LSTM, K=256 (A = [x_t | h]): fused cell epilogue. grid.y = 4.
// ==================================================================================
template <int MODE>
__global__ __launch_bounds__(256, 2) void gemm_f16(
    const u32* __restrict__ A0, int ldap,      // pairs/row
    const u32* __restrict__ A1,                // MODE1 h (ld 64)
    const u32* __restrict__ Bh, int ldbp,
    const float* __restrict__ bias,
    float* __restrict__ C, float* __restrict__ hsacc,
    u16* __restrict__ ho_, float* __restrict__ hta)
{
    __shared__ __align__(16) u32 sh[8192];   // 3 x 8KB staging; epilogue reuses 32KB
    float* gtile = (float*)sh;               // epilogue [64][128]

    const int tid = threadIdx.x, lane = tid & 31;
    const int warpId = tid >> 5;
    const int warpM = warpId >> 2, warpN = warpId & 3;
    const int rowBase = blockIdx.x * 128;
    const int colBase = blockIdx.y * 128;

    const u32 smb = smem_u32(sh);

    float acc[4][4][4];
#pragma unroll
    for (int a = 0; a < 4; a++)
#pragma unroll
        for (int b = 0; b < 4; b++)
#pragma unroll
            for (int c = 0; c < 4; c++) acc[a][b][c] = 0.f;

    const int NCH = MODE ? 16 : 8;
    const int r_ = tid >> 1, half_ = tid & 1;        // staging coords
    const u32 stA = swz(r_, half_);                  // store offsets (constant over chunks)
    const int rowOK = (rowBase + r_ < NN) ? 16 : 0;
    const int rowC = (rowBase + r_ < NN) ? (rowBase + r_) : 0;   // clamped
    const int gcB = (MODE ? colBase : 0) + r_;

    // stage buffer: A[0,4096) B[4096,8192); stride 8192; 3 stages
    auto issue_chunk = [&](int ch) {
        u32 bufoff = (u32)((ch % 3) * 8192);
        const u32* a_;
        int po, ld;
        if (MODE == 1 && ch >= 8) { a_ = A1; po = (ch - 8) * 8 + half_ * 4; ld = 64; }
        else                      { a_ = A0; po = ch * 8 + half_ * 4; ld = ldap; }
        CP_ASYNC16(smb + bufoff + stA,        a_ + (size_t)rowC * ld + po, rowOK);
        int pb = ch * 8 + half_ * 4;
        CP_ASYNC16(smb + bufoff + 4096 + stA, Bh + (size_t)gcB * ldbp + pb, 16);
    };

    issue_chunk(0); CP_COMMIT();
    issue_chunk(1); CP_COMMIT();

    for (int ch = 0; ch < NCH; ch++) {
        if (ch + 1 < NCH) asm volatile("cp.async.wait_group 1;");
        else              asm volatile("cp.async.wait_group 0;");
        __syncthreads();
        const u32 bufoff = (u32)((ch % 3) * 8192);
        const u32 smA = smb + bufoff;
        const u32 smB = smb + bufoff + 4096;
        uint4 ah[4];
        uint2 bb[4];
        {
            int ra = lane & 15, ha = lane >> 4;
#pragma unroll
            for (int mi = 0; mi < 4; mi++) {
                int row = warpM * 64 + mi * 16 + ra;
                LDSM_X4(ah[mi], smA + swz(row, ha));
            }
            int rb = lane & 7, hb = (lane >> 3) & 1;
#pragma unroll
            for (int ni = 0; ni < 4; ni++) {
                int n = warpN * 32 + ni * 8 + rb;
                LDSM_X2(bb[ni], smB + swz(n, hb));
            }
        }
#pragma unroll
        for (int ni = 0; ni < 4; ni++)
#pragma unroll
            for (int mi = 0; mi < 4; mi++)
                mma16(acc[mi][ni], ah[mi], bb[ni].x, bb[ni].y);
        if (ch + 2 < NCH) { issue_chunk(ch + 2); CP_COMMIT(); }
    }

    // ---- epilogue: stage through shared, 2 row-halves of 64 ----
    float csum[4] = {0.f, 0.f, 0.f, 0.f};
    const int cq = tid & 31;

    for (int half = 0; half < 2; half++) {
        __syncthreads();
        if (warpM == half) {
#pragma unroll
            for (int mi = 0; mi < 4; mi++) {
#pragma unroll
                for (int ni = 0; ni < 4; ni++) {
                    int rloc = mi * 16 + (lane >> 2);
                    int cloc = warpN * 32 + ni * 8 + (lane & 3) * 2;
                    float b0v = bias[colBase + cloc];
                    float b1v = bias[colBase + cloc + 1];
                    gtile[rloc * 128 + cloc]           = acc[mi][ni][0] + b0v;
                    gtile[rloc * 128 + cloc + 1]       = acc[mi][ni][1] + b1v;
                    gtile[(rloc + 8) * 128 + cloc]     = acc[mi][ni][2] + b0v;
                    gtile[(rloc + 8) * 128 + cloc + 1] = acc[mi][ni][3] + b1v;
                }
            }
        }
        __syncthreads();
#pragma unroll
        for (int i = 0; i < 8; i++) {
            int e = tid + i * 256;
            int rloc = e >> 5;
            int row = rowBase + half * 64 + rloc;
            if (MODE == 0) {
                float4 gv = *(const float4*)&gtile[rloc * 128 + cq * 4];
                float4 ov;
                ov.x = gelu_exact(gv.x);
                ov.y = gelu_exact(gv.y);
                ov.z = gelu_exact(gv.z);
                ov.w = gelu_exact(gv.w);
                if (row < NN) {
                    if (C != nullptr)
                        *(float4*)(C + (size_t)row * D + cq * 4) = ov;
                    csum[0] += ov.x; csum[1] += ov.y; csum[2] += ov.z; csum[3] += ov.w;
                }
            } else {
                if (row < NN) {
                    float4 gv = *(const float4*)&gtile[rloc * 128 + cq * 4];
                    int fg = blockIdx.y * 32 + cq;
                    size_t idx = (size_t)row * D + fg;
                    float cp = g_c[idx];
                    float cn = sigmoidf_(gv.y) * cp + sigmoidf_(gv.x) * tanhf(gv.z);
                    float ho = sigmoidf_(gv.w) * tanhf(cn);
                    g_c[idx] = cn;
                    hta[idx] += ho;
                    ho_[idx] = h1(ho);
                }
            }
        }
    }
    if (MODE == 0 && hsacc != nullptr) {
#pragma unroll
        for (int j = 0; j < 4; j++) atomicAdd(&hsacc[cq * 4 + j], csum[j]);
    }
}

__global__ void finalize_kernel(float* __restrict__ out) {
    int idx = blockIdx.x * blockDim.x + threadIdx.x;
    if (idx < TT * D) out[idx] = g_hs[idx] * (1.0f / (float)NN);
    if (idx < NN * D) out[TT * D + idx] *= (1.0f / (float)TT);
}

// ---------------- launch ----------------
extern "C" void kernel_launch(void* const* d_in, const int* in_sizes, int n_in,
                              void* d_out, int out_size) {
    const float* h    = (const float*)d_in[0];
    const int*   src  = (const int*)d_in[1];
    const int*   dst  = (const int*)d_in[2];
    const float* Wg1  = (const float*)d_in[3];
    const float* bg1  = (const float*)d_in[4];
    const float* Wg2  = (const float*)d_in[5];
    const float* bg2  = (const float*)d_in[6];
    const float* w_ih = (const float*)d_in[7];
    const float* w_hh = (const float*)d_in[8];
    const float* b_ih = (const float*)d_in[9];
    const float* b_hh = (const float*)d_in[10];

    float* out    = (float*)d_out;
    float* out_ht = out + TT * D;

    u16 *pxh, *pmh, *ph0, *ph1, *pwlh, *pw1h, *pw2h;
    float *pxact, *pbp, *phs;
    cudaGetSymbolAddress((void**)&pxh, g_xh);
    cudaGetSymbolAddress((void**)&pmh, g_mh);
    cudaGetSymbolAddress((void**)&ph0, g_h0);
    cudaGetSymbolAddress((void**)&ph1, g_h1);
    cudaGetSymbolAddress((void**)&pwlh, g_wlh);
    cudaGetSymbolAddress((void**)&pw1h, g_w1h);
    cudaGetSymbolAddress((void**)&pw2h, g_w2h);
    cudaGetSymbolAddress((void**)&pxact, g_xact);
    cudaGetSymbolAddress((void**)&pbp, g_biasp);
    cudaGetSymbolAddress((void**)&phs, g_hs);

    // fork/join resources (host objects only)
    cudaStream_t s2;
    cudaStreamCreateWithFlags(&s2, cudaStreamNonBlocking);
    cudaEvent_t e1, e2;
    cudaEventCreateWithFlags(&e1, cudaEventDisableTiming);
    cudaEventCreateWithFlags(&e2, cudaEventDisableTiming);

    // common setup on main stream
    init_kernel<<<(NN * D + 255) / 256, 256>>>(out_ht);
    wlprep_kernel<<<(512 * 256 + 255) / 256, 256>>>(w_ih, w_hh, b_ih, b_hh);
    convh_kernel<<<(int)(((size_t)NN * TT * D / 4 + 255) / 256), 256>>>(h);

    // fork: LSTM chain on s2
    cudaEventRecord(e1, 0);
    cudaStreamWaitEvent(s2, e1, 0);

    const int gx = (NN + 127) / 128;   // 391
    u16 *hin = ph0, *hout = ph1;
    for (int t = 0; t < TT; t++) {
        gemm_f16<1><<<dim3(gx, 4), 256, 0, s2>>>(
            (u32*)pxh + (size_t)t * 64, TT * 64,
            (u32*)hin,
            (u32*)pwlh, 128, pbp,
            nullptr, nullptr, hout, out_ht);
        u16* tmp = hin; hin = hout; hout = tmp;
    }
    cudaEventRecord(e2, s2);

    // graph chain on main stream
    hist_kernel<<<(EE + 255) / 256, 256>>>(src, dst);
    norm_kernel<<<(NN + 255) / 256, 256>>>();
    wgprep_kernel<<<(2 * 128 * 128 + 255) / 256, 256>>>(Wg1, Wg2);
    scan_kernel<<<1, 1024>>>();
    scatter_kernel<<<(EE + 255) / 256, 256>>>(src, dst);

    int spmm_blocks = (NN * 32 + 255) / 256;
    for (int t = 0; t < TT; t++) {
        spmm_kernel<<<spmm_blocks, 256>>>(h + t * D, TT * D);
        gemm_f16<0><<<dim3(gx, 1), 256>>>((u32*)pmh, 64, nullptr,
                                          (u32*)pw1h, 64, bg1,
                                          pxact, nullptr, nullptr, nullptr);
        spmm_kernel<<<spmm_blocks, 256>>>(pxact, D);
        gemm_f16<0><<<dim3(gx, 1), 256>>>((u32*)pmh, 64, nullptr,
                                          (u32*)pw2h, 64, bg2,
                                          nullptr, phs + t * D, nullptr, nullptr);
    }

    // join and finalize
    cudaStreamWaitEvent(0, e2, 0);
    finalize_kernel<<<(NN * D + 255) / 256, 256>>>(out);
}

// round 15
// speedup vs baseline: 1.8804x; 1.0228x over previous
#include <cuda_runtime.h>
#include <cuda_fp16.h>
#include <math.h>
#include <stdint.h>

#define NN 50000
#define EE 800000
#define TT 12
#define D  128

typedef unsigned short u16;
typedef unsigned int   u32;

// ---------------- scratch ----------------
__device__ float g_norm_src[NN], g_norm_dst[NN];
__device__ int g_ocnt[NN], g_cnt[NN + 1], g_rowptr[NN + 1], g_cursor[NN];
__device__ int g_srcsorted[EE];
__device__ __align__(16) u16 g_xh[(size_t)NN * TT * D];    // x fp16 (pair-packed along k)
__device__ __align__(16) u16 g_mh[(size_t)NN * D];         // spmm out fp16
__device__ __align__(16) u16 g_x1h[(size_t)NN * D];        // layer-1 act fp16
__device__ __align__(16) u16 g_h0[(size_t)NN * D], g_h1[(size_t)NN * D];  // LSTM h fp16
__device__ __align__(16) float g_c[(size_t)NN * D];
__device__ __align__(16) u16 g_wlh[512 * 256];             // [n][k] fp16, quad-permuted rows
__device__ __align__(16) u16 g_w1h[128 * 128];             // [n][k] fp16
__device__ __align__(16) u16 g_w2h[128 * 128];
__device__ float g_biasp[512];
__device__ float g_hs[TT * D];

// ---------------- helpers ----------------
__device__ __forceinline__ float gelu_exact(float v) {
    return 0.5f * v * (1.0f + erff(v * 0.70710678118654752f));
}
__device__ __forceinline__ float sigmoidf_(float v) {
    return 1.0f / (1.0f + __expf(-v));
}
__device__ __forceinline__ u16 h1(float x) {
    __half hh = __float2half_rn(x);
    return *(u16*)&hh;
}
__device__ __forceinline__ u32 smem_u32(const void* p) {
    u32 a;
    asm("{ .reg .u64 t; cvta.to.shared.u64 t, %1; cvt.u32.u64 %0, t; }" : "=r"(a) : "l"(p));
    return a;
}
__device__ __forceinline__ void mma16(float (&c)[4], uint4 a, u32 b0, u32 b1) {
    asm volatile(
        "mma.sync.aligned.m16n8k16.row.col.f32.f16.f16.f32 "
        "{%0,%1,%2,%3},{%4,%5,%6,%7},{%8,%9},{%0,%1,%2,%3};\n"
        : "+f"(c[0]), "+f"(c[1]), "+f"(c[2]), "+f"(c[3])
        : "r"(a.x), "r"(a.y), "r"(a.z), "r"(a.w), "r"(b0), "r"(b1));
}
#define LDSM_X4(d, a) \
    asm volatile("ldmatrix.sync.aligned.m8n8.x4.shared.b16 {%0,%1,%2,%3}, [%4];" \
                 : "=r"((d).x), "=r"((d).y), "=r"((d).z), "=r"((d).w) : "r"(a))
#define LDSM_X2(d, a) \
    asm volatile("ldmatrix.sync.aligned.m8n8.x2.shared.b16 {%0,%1}, [%2];" \
                 : "=r"((d).x), "=r"((d).y) : "r"(a))
#define CP_ASYNC16(dst, src, sz) \
    asm volatile("cp.async.cg.shared.global [%0], [%1], 16, %2;" \
                 :: "r"(dst), "l"(src), "r"(sz))
#define CP_COMMIT() asm volatile("cp.async.commit_group;")
// swizzled byte offset inside a 128-row x 32B tile
__device__ __forceinline__ u32 swz(int row, int half) {
    return (u32)(row * 32 + ((half << 4) ^ ((row & 4) << 2)));
}

// ---------------- setup kernels ----------------
__global__ void init_kernel(float* __restrict__ out_ht) {
    int i = blockIdx.x * blockDim.x + threadIdx.x;
    if (i < NN * D) {
        g_c[i] = 0.0f;
        g_h0[i] = 0;
        out_ht[i] = 0.0f;
    }
    if (i < NN) { g_ocnt[i] = 0; g_cnt[i] = 0; }
    if (i == 0) g_cnt[NN] = 0;
    if (i < TT * D) g_hs[i] = 0.0f;
}
__global__ void hist_kernel(const int* __restrict__ src, const int* __restrict__ dst) {
    int e = blockIdx.x * blockDim.x + threadIdx.x;
    if (e < EE) {
        atomicAdd(&g_ocnt[src[e]], 1);
        atomicAdd(&g_cnt[dst[e]], 1);
    }
}
__global__ void norm_kernel() {
    int i = blockIdx.x * blockDim.x + threadIdx.x;
    if (i < NN) {
        g_norm_src[i] = rsqrtf(fmaxf((float)g_ocnt[i], 1.0f));
        g_norm_dst[i] = rsqrtf(fmaxf((float)g_cnt[i], 1.0f));
    }
}
__global__ void scan_kernel() {
    __shared__ int ps[1024];
    const int CH = (NN + 1023) / 1024;
    int t = threadIdx.x;
    int beg = t * CH, end = min(beg + CH, NN);
    int s = 0;
    for (int i = beg; i < end; i++) s += g_cnt[i];
    ps[t] = s;
    __syncthreads();
    if (t == 0) {
        int a = 0;
        for (int i = 0; i < 1024; i++) { int v = ps[i]; ps[i] = a; a += v; }
    }
    __syncthreads();
    int off = ps[t];
    for (int i = beg; i < end; i++) {
        g_rowptr[i] = off;
        g_cursor[i] = off;
        off += g_cnt[i];
    }
    if (t == 1023) g_rowptr[NN] = off;
}
__global__ void scatter_kernel(const int* __restrict__ src, const int* __restrict__ dst) {
    int e = blockIdx.x * blockDim.x + threadIdx.x;
    if (e < EE) {
        int d = dst[e];
        int p = atomicAdd(&g_cursor[d], 1);
        g_srcsorted[p] = src[e];
    }
}
__global__ void convh_kernel(const float* __restrict__ h) {
    size_t q = (size_t)blockIdx.x * blockDim.x + threadIdx.x;
    if (q >= (size_t)NN * TT * D / 4) return;
    float4 v = ((const float4*)h)[q];
    ((uint2*)g_xh)[q] = make_uint2((u32)h1(v.x) | ((u32)h1(v.y) << 16),
                                   (u32)h1(v.z) | ((u32)h1(v.w) << 16));
}
// LSTM weights: row_out j*4+g <- row_in g*128+j, cols [w_ih|w_hh]; fp16
__global__ void wlprep_kernel(const float* __restrict__ w_ih, const float* __restrict__ w_hh,
                              const float* __restrict__ b_ih, const float* __restrict__ b_hh) {
    int idx = blockIdx.x * blockDim.x + threadIdx.x;
    if (idx >= 512 * 256) return;
    int ro = idx >> 8, k = idx & 255;
    int ri = (ro & 3) * D + (ro >> 2);
    float v = (k < D) ? w_ih[ri * D + k] : w_hh[ri * D + (k - D)];
    g_wlh[idx] = h1(v);
    if (k == 0) g_biasp[ro] = b_ih[ri] + b_hh[ri];
}
// graph weights: B[n][k] = W[k][n]; fp16
__global__ void wgprep_kernel(const float* __restrict__ Wg1, const float* __restrict__ Wg2) {
    int idx = blockIdx.x * blockDim.x + threadIdx.x;
    if (idx >= 2 * 128 * 128) return;
    int sel = idx >> 14, e = idx & 16383;
    int n = e >> 7, k = e & 127;
    float v = sel ? Wg2[k * 128 + n] : Wg1[k * 128 + n];
    if (sel) g_w2h[e] = h1(v);
    else     g_w1h[e] = h1(v);
}

// ---------------- SpMM: fp16 gather, fp32 accumulate, fp16 out ----------------
__global__ __launch_bounds__(256) void spmm_kernel(const u32* __restrict__ X, int ldp) {
    int w = (blockIdx.x * blockDim.x + threadIdx.x) >> 5;
    int lane = threadIdx.x & 31;
    if (w >= NN) return;
    int s0 = g_rowptr[w], s1 = g_rowptr[w + 1];
    float4 acc = make_float4(0.f, 0.f, 0.f, 0.f);
    for (int base = s0; base < s1; base += 32) {
        int n = min(32, s1 - base);
        int s = 0; float ns = 0.f;
        if (lane < n) {
            s = g_srcsorted[base + lane];
            ns = g_norm_src[s];
        }
        for (int j = 0; j < n; j++) {
            int   sj = __shfl_sync(0xffffffffu, s, j);
            float nj = __shfl_sync(0xffffffffu, ns, j);
            uint2 v = *(const uint2*)(X + (size_t)sj * ldp + lane * 2);
            float2 f01 = __half22float2(*reinterpret_cast<const __half2*>(&v.x));
            float2 f23 = __half22float2(*reinterpret_cast<const __half2*>(&v.y));
            acc.x += f01.x * nj; acc.y += f01.y * nj;
            acc.z += f23.x * nj; acc.w += f23.y * nj;
        }
    }
    float nd = g_norm_dst[w];
    size_t q = ((size_t)w * D + lane * 4) >> 2;
    ((uint2*)g_mh)[q] = make_uint2((u32)h1(acc.x * nd) | ((u32)h1(acc.y * nd) << 16),
                                   (u32)h1(acc.z * nd) | ((u32)h1(acc.w * nd) << 16));
}

// ==================================================================================
// fp16 GEMM, mma.m16n8k16, BM=128 BN=128 BK=16.
// 3-stage cp.async pipeline, ONE __syncthreads per chunk, ldmatrix, term-major mma.
// MODE 0: graph conv, K=128: Ch = fp16(gelu(A@B^T + bias)); opt store, opt hs colsum.
// MODE 1: LSTM, K=256 (A = [x_t | h]): fused cell epilogue. grid.y = 4.
// ==================================================================================
template <int MODE>
__global__ __launch_bounds__(256, 2) void gemm_f16(
    const u32* __restrict__ A0, int ldap,      // pairs/row
    const u32* __restrict__ A1,                // MODE1 h (ld 64)
    const u32* __restrict__ Bh, int ldbp,
    const float* __restrict__ bias,
    u16* __restrict__ Ch, float* __restrict__ hsacc,
    u16* __restrict__ ho_, float* __restrict__ hta)
{
    __shared__ __align__(16) u32 sh[8192];   // 3 x 8KB staging; epilogue reuses 32KB
    float* gtile = (float*)sh;               // epilogue [64][128]

    const int tid = threadIdx.x, lane = tid & 31;
    const int warpId = tid >> 5;
    const int warpM = warpId >> 2, warpN = warpId & 3;
    const int rowBase = blockIdx.x * 128;
    const int colBase = blockIdx.y * 128;

    const u32 smb = smem_u32(sh);

    float acc[4][4][4];
#pragma unroll
    for (int a = 0; a < 4; a++)
#pragma unroll
        for (int b = 0; b < 4; b++)
#pragma unroll
            for (int c = 0; c < 4; c++) acc[a][b][c] = 0.f;

    const int NCH = MODE ? 16 : 8;
    const int r_ = tid >> 1, half_ = tid & 1;        // staging coords
    const u32 stA = swz(r_, half_);                  // store offsets (constant over chunks)
    const int rowOK = (rowBase + r_ < NN) ? 16 : 0;
    const int rowC = (rowBase + r_ < NN) ? (rowBase + r_) : 0;   // clamped
    const int gcB = (MODE ? colBase : 0) + r_;

    // stage buffer: A[0,4096) B[4096,8192); stride 8192; 3 stages
    auto issue_chunk = [&](int ch) {
        u32 bufoff = (u32)((ch % 3) * 8192);
        const u32* a_;
        int po, ld;
        if (MODE == 1 && ch >= 8) { a_ = A1; po = (ch - 8) * 8 + half_ * 4; ld = 64; }
        else                      { a_ = A0; po = ch * 8 + half_ * 4; ld = ldap; }
        CP_ASYNC16(smb + bufoff + stA,        a_ + (size_t)rowC * ld + po, rowOK);
        int pb = ch * 8 + half_ * 4;
        CP_ASYNC16(smb + bufoff + 4096 + stA, Bh + (size_t)gcB * ldbp + pb, 16);
    };

    issue_chunk(0); CP_COMMIT();
    issue_chunk(1); CP_COMMIT();

    for (int ch = 0; ch < NCH; ch++) {
        if (ch + 1 < NCH) asm volatile("cp.async.wait_group 1;");
        else              asm volatile("cp.async.wait_group 0;");
        __syncthreads();
        const u32 bufoff = (u32)((ch % 3) * 8192);
        const u32 smA = smb + bufoff;
        const u32 smB = smb + bufoff + 4096;
        uint4 ah[4];
        uint2 bb[4];
        {
            int ra = lane & 15, ha = lane >> 4;
#pragma unroll
            for (int mi = 0; mi < 4; mi++) {
                int row = warpM * 64 + mi * 16 + ra;
                LDSM_X4(ah[mi], smA + swz(row, ha));
            }
            int rb = lane & 7, hb = (lane >> 3) & 1;
#pragma unroll
            for (int ni = 0; ni < 4; ni++) {
                int n = warpN * 32 + ni * 8 + rb;
                LDSM_X2(bb[ni], smB + swz(n, hb));
            }
        }
#pragma unroll
        for (int ni = 0; ni < 4; ni++)
#pragma unroll
            for (int mi = 0; mi < 4; mi++)
                mma16(acc[mi][ni], ah[mi], bb[ni].x, bb[ni].y);
        if (ch + 2 < NCH) { issue_chunk(ch + 2); CP_COMMIT(); }
    }

    // ---- epilogue: stage through shared, 2 row-halves of 64 ----
    float csum[4] = {0.f, 0.f, 0.f, 0.f};
    const int cq = tid & 31;

    for (int half = 0; half < 2; half++) {
        __syncthreads();
        if (warpM == half) {
#pragma unroll
            for (int mi = 0; mi < 4; mi++) {
#pragma unroll
                for (int ni = 0; ni < 4; ni++) {
                    int rloc = mi * 16 + (lane >> 2);
                    int cloc = warpN * 32 + ni * 8 + (lane & 3) * 2;
                    float b0v = bias[colBase + cloc];
                    float b1v = bias[colBase + cloc + 1];
                    gtile[rloc * 128 + cloc]           = acc[mi][ni][0] + b0v;
                    gtile[rloc * 128 + cloc + 1]       = acc[mi][ni][1] + b1v;
                    gtile[(rloc + 8) * 128 + cloc]     = acc[mi][ni][2] + b0v;
                    gtile[(rloc + 8) * 128 + cloc + 1] = acc[mi][ni][3] + b1v;
                }
            }
        }
        __syncthreads();
#pragma unroll
        for (int i = 0; i < 8; i++) {
            int e = tid + i * 256;
            int rloc = e >> 5;
            int row = rowBase + half * 64 + rloc;
            if (MODE == 0) {
                float4 gv = *(const float4*)&gtile[rloc * 128 + cq * 4];
                float4 ov;
                ov.x = gelu_exact(gv.x);
                ov.y = gelu_exact(gv.y);
                ov.z = gelu_exact(gv.z);
                ov.w = gelu_exact(gv.w);
                if (row < NN) {
                    if (Ch != nullptr) {
                        uint2 pk;
                        pk.x = (u32)h1(ov.x) | ((u32)h1(ov.y) << 16);
                        pk.y = (u32)h1(ov.z) | ((u32)h1(ov.w) << 16);
                        *(uint2*)(Ch + (size_t)row * D + cq * 4) = pk;
                    }
                    csum[0] += ov.x; csum[1] += ov.y; csum[2] += ov.z; csum[3] += ov.w;
                }
            } else {
                if (row < NN) {
                    float4 gv = *(const float4*)&gtile[rloc * 128 + cq * 4];
                    int fg = blockIdx.y * 32 + cq;
                    size_t idx = (size_t)row * D + fg;
                    float cp = g_c[idx];
                    float cn = sigmoidf_(gv.y) * cp + sigmoidf_(gv.x) * tanhf(gv.z);
                    float ho = sigmoidf_(gv.w) * tanhf(cn);
                    g_c[idx] = cn;
                    hta[idx] += ho;
                    ho_[idx] = h1(ho);
                }
            }
        }
    }
    if (MODE == 0 && hsacc != nullptr) {
#pragma unroll
        for (int j = 0; j < 4; j++) atomicAdd(&hsacc[cq * 4 + j], csum[j]);
    }
}

__global__ void finalize_kernel(float* __restrict__ out) {
    int idx = blockIdx.x * blockDim.x + threadIdx.x;
    if (idx < TT * D) out[idx] = g_hs[idx] * (1.0f / (float)NN);
    if (idx < NN * D) out[TT * D + idx] *= (1.0f / (float)TT);
}

// ---------------- launch ----------------
extern "C" void kernel_launch(void* const* d_in, const int* in_sizes, int n_in,
                              void* d_out, int out_size) {
    const float* h    = (const float*)d_in[0];
    const int*   src  = (const int*)d_in[1];
    const int*   dst  = (const int*)d_in[2];
    const float* Wg1  = (const float*)d_in[3];
    const float* bg1  = (const float*)d_in[4];
    const float* Wg2  = (const float*)d_in[5];
    const float* bg2  = (const float*)d_in[6];
    const float* w_ih = (const float*)d_in[7];
    const float* w_hh = (const float*)d_in[8];
    const float* b_ih = (const float*)d_in[9];
    const float* b_hh = (const float*)d_in[10];

    float* out    = (float*)d_out;
    float* out_ht = out + TT * D;

    u16 *pxh, *pmh, *px1h, *ph0, *ph1, *pwlh, *pw1h, *pw2h;
    float *pbp, *phs;
    cudaGetSymbolAddress((void**)&pxh, g_xh);
    cudaGetSymbolAddress((void**)&pmh, g_mh);
    cudaGetSymbolAddress((void**)&px1h, g_x1h);
    cudaGetSymbolAddress((void**)&ph0, g_h0);
    cudaGetSymbolAddress((void**)&ph1, g_h1);
    cudaGetSymbolAddress((void**)&pwlh, g_wlh);
    cudaGetSymbolAddress((void**)&pw1h, g_w1h);
    cudaGetSymbolAddress((void**)&pw2h, g_w2h);
    cudaGetSymbolAddress((void**)&pbp, g_biasp);
    cudaGetSymbolAddress((void**)&phs, g_hs);

    // fork/join resources (host objects only)
    cudaStream_t s2;
    cudaStreamCreateWithFlags(&s2, cudaStreamNonBlocking);
    cudaEvent_t e1, e2;
    cudaEventCreateWithFlags(&e1, cudaEventDisableTiming);
    cudaEventCreateWithFlags(&e2, cudaEventDisableTiming);

    // common setup on main stream
    init_kernel<<<(NN * D + 255) / 256, 256>>>(out_ht);
    wlprep_kernel<<<(512 * 256 + 255) / 256, 256>>>(w_ih, w_hh, b_ih, b_hh);
    convh_kernel<<<(int)(((size_t)NN * TT * D / 4 + 255) / 256), 256>>>(h);

    // fork: LSTM chain on s2
    cudaEventRecord(e1, 0);
    cudaStreamWaitEvent(s2, e1, 0);

    const int gx = (NN + 127) / 128;   // 391
    u16 *hin = ph0, *hout = ph1;
    for (int t = 0; t < TT; t++) {
        gemm_f16<1><<<dim3(gx, 4), 256, 0, s2>>>(
            (u32*)pxh + (size_t)t * 64, TT * 64,
            (u32*)hin,
            (u32*)pwlh, 128, pbp,
            nullptr, nullptr, hout, out_ht);
        u16* tmp = hin; hin = hout; hout = tmp;
    }
    cudaEventRecord(e2, s2);

    // graph chain on main stream
    hist_kernel<<<(EE + 255) / 256, 256>>>(src, dst);
    norm_kernel<<<(NN + 255) / 256, 256>>>();
    wgprep_kernel<<<(2 * 128 * 128 + 255) / 256, 256>>>(Wg1, Wg2);
    scan_kernel<<<1, 1024>>>();
    scatter_kernel<<<(EE + 255) / 256, 256>>>(src, dst);

    int spmm_blocks = (NN * 32 + 255) / 256;
    for (int t = 0; t < TT; t++) {
        spmm_kernel<<<spmm_blocks, 256>>>((u32*)pxh + (size_t)t * 64, TT * 64);
        gemm_f16<0><<<dim3(gx, 1), 256>>>((u32*)pmh, 64, nullptr,
                                          (u32*)pw1h, 64, bg1,
                                          px1h, nullptr, nullptr, nullptr);
        spmm_kernel<<<spmm_blocks, 256>>>((u32*)px1h, 64);
        gemm_f16<0><<<dim3(gx, 1), 256>>>((u32*)pmh, 64, nullptr,
                                          (u32*)pw2h, 64, bg2,
                                          nullptr, phs + t * D, nullptr, nullptr);
    }

    // join and finalize
    cudaStreamWaitEvent(0, e2, 0);
    finalize_kernel<<<(NN * D + 255) / 256, 256>>>(out);
}

// round 17
// speedup vs baseline: 2.0173x; 1.0728x over previous
#include <cuda_runtime.h>
#include <cuda_fp16.h>
#include <math.h>
#include <stdint.h>

#define NN 50000
#define EE 800000
#define TT 12
#define D  128
#define GX 391   // ceil(NN/128)

typedef unsigned short u16;
typedef unsigned int   u32;

// ---------------- scratch ----------------
__device__ float g_norm_src[NN], g_norm_dst[NN];
__device__ int g_ocnt[NN], g_cnt[NN + 1], g_rowptr[NN + 1], g_cursor[NN];
__device__ int g_srcsorted[EE];
__device__ __align__(16) u16 g_xh[(size_t)NN * TT * D];    // x fp16 (pair-packed along k)
__device__ __align__(16) u16 g_mb[(size_t)NN * TT * D];    // batched spmm out fp16 [t][n][128]
__device__ __align__(16) u16 g_x1b[(size_t)NN * TT * D];   // batched layer-1 act fp16
__device__ __align__(16) u16 g_h0[(size_t)NN * D], g_h1[(size_t)NN * D];  // LSTM h fp16
__device__ __align__(16) float g_c[(size_t)NN * D];
__device__ __align__(16) u16 g_wlh[512 * 256];             // [n][k] fp16, quad-permuted rows
__device__ __align__(16) u16 g_w1h[128 * 128];             // [n][k] fp16
__device__ __align__(16) u16 g_w2h[128 * 128];
__device__ float g_biasp[512];
__device__ float g_hs[TT * D];

// ---------------- helpers ----------------
__device__ __forceinline__ float gelu_exact(float v) {
    return 0.5f * v * (1.0f + erff(v * 0.70710678118654752f));
}
__device__ __forceinline__ float sigmoidf_(float v) {
    return 1.0f / (1.0f + __expf(-v));
}
__device__ __forceinline__ u16 h1(float x) {
    __half hh = __float2half_rn(x);
    return *(u16*)&hh;
}
__device__ __forceinline__ u32 smem_u32(const void* p) {
    u32 a;
    asm("{ .reg .u64 t; cvta.to.shared.u64 t, %1; cvt.u32.u64 %0, t; }" : "=r"(a) : "l"(p));
    return a;
}
__device__ __forceinline__ void mma16(float (&c)[4], uint4 a, u32 b0, u32 b1) {
    asm volatile(
        "mma.sync.aligned.m16n8k16.row.col.f32.f16.f16.f32 "
        "{%0,%1,%2,%3},{%4,%5,%6,%7},{%8,%9},{%0,%1,%2,%3};\n"
        : "+f"(c[0]), "+f"(c[1]), "+f"(c[2]), "+f"(c[3])
        : "r"(a.x), "r"(a.y), "r"(a.z), "r"(a.w), "r"(b0), "r"(b1));
}
#define LDSM_X4(d, a) \
    asm volatile("ldmatrix.sync.aligned.m8n8.x4.shared.b16 {%0,%1,%2,%3}, [%4];" \
                 : "=r"((d).x), "=r"((d).y), "=r"((d).z), "=r"((d).w) : "r"(a))
#define LDSM_X2(d, a) \
    asm volatile("ldmatrix.sync.aligned.m8n8.x2.shared.b16 {%0,%1}, [%2];" \
                 : "=r"((d).x), "=r"((d).y) : "r"(a))
#define CP_ASYNC16(dst, src, sz) \
    asm volatile("cp.async.cg.shared.global [%0], [%1], 16, %2;" \
                 :: "r"(dst), "l"(src), "r"(sz))
#define CP_COMMIT() asm volatile("cp.async.commit_group;")
// swizzled byte offset inside a 128-row x 32B tile
__device__ __forceinline__ u32 swz(int row, int half) {
    return (u32)(row * 32 + ((half << 4) ^ ((row & 4) << 2)));
}

// ---------------- setup kernels ----------------
__global__ void init_kernel(float* __restrict__ out_ht) {
    int i = blockIdx.x * blockDim.x + threadIdx.x;
    if (i < NN * D) {
        g_c[i] = 0.0f;
        g_h0[i] = 0;
        out_ht[i] = 0.0f;
    }
    if (i < NN) { g_ocnt[i] = 0; g_cnt[i] = 0; }
    if (i == 0) g_cnt[NN] = 0;
    if (i < TT * D) g_hs[i] = 0.0f;
}
__global__ void hist_kernel(const int* __restrict__ src, const int* __restrict__ dst) {
    int e = blockIdx.x * blockDim.x + threadIdx.x;
    if (e < EE) {
        atomicAdd(&g_ocnt[src[e]], 1);
        atomicAdd(&g_cnt[dst[e]], 1);
    }
}
__global__ void norm_kernel() {
    int i = blockIdx.x * blockDim.x + threadIdx.x;
    if (i < NN) {
        g_norm_src[i] = rsqrtf(fmaxf((float)g_ocnt[i], 1.0f));
        g_norm_dst[i] = rsqrtf(fmaxf((float)g_cnt[i], 1.0f));
    }
}
__global__ void scan_kernel() {
    __shared__ int ps[1024];
    const int CH = (NN + 1023) / 1024;
    int t = threadIdx.x;
    int beg = t * CH, end = min(beg + CH, NN);
    int s = 0;
    for (int i = beg; i < end; i++) s += g_cnt[i];
    ps[t] = s;
    __syncthreads();
    if (t == 0) {
        int a = 0;
        for (int i = 0; i < 1024; i++) { int v = ps[i]; ps[i] = a; a += v; }
    }
    __syncthreads();
    int off = ps[t];
    for (int i = beg; i < end; i++) {
        g_rowptr[i] = off;
        g_cursor[i] = off;
        off += g_cnt[i];
    }
    if (t == 1023) g_rowptr[NN] = off;
}
__global__ void scatter_kernel(const int* __restrict__ src, const int* __restrict__ dst) {
    int e = blockIdx.x * blockDim.x + threadIdx.x;
    if (e < EE) {
        int d = dst[e];
        int p = atomicAdd(&g_cursor[d], 1);
        g_srcsorted[p] = src[e];
    }
}
__global__ void convh_kernel(const float* __restrict__ h) {
    size_t q = (size_t)blockIdx.x * blockDim.x + threadIdx.x;
    if (q >= (size_t)NN * TT * D / 4) return;
    float4 v = ((const float4*)h)[q];
    ((uint2*)g_xh)[q] = make_uint2((u32)h1(v.x) | ((u32)h1(v.y) << 16),
                                   (u32)h1(v.z) | ((u32)h1(v.w) << 16));
}
// LSTM weights: row_out j*4+g <- row_in g*128+j, cols [w_ih|w_hh]; fp16
__global__ void wlprep_kernel(const float* __restrict__ w_ih, const float* __restrict__ w_hh,
                              const float* __restrict__ b_ih, const float* __restrict__ b_hh) {
    int idx = blockIdx.x * blockDim.x + threadIdx.x;
    if (idx >= 512 * 256) return;
    int ro = idx >> 8, k = idx & 255;
    int ri = (ro & 3) * D + (ro >> 2);
    float v = (k < D) ? w_ih[ri * D + k] : w_hh[ri * D + (k - D)];
    g_wlh[idx] = h1(v);
    if (k == 0) g_biasp[ro] = b_ih[ri] + b_hh[ri];
}
// graph weights: B[n][k] = W[k][n]; fp16
__global__ void wgprep_kernel(const float* __restrict__ Wg1, const float* __restrict__ Wg2) {
    int idx = blockIdx.x * blockDim.x + threadIdx.x;
    if (idx >= 2 * 128 * 128) return;
    int sel = idx >> 14, e = idx & 16383;
    int n = e >> 7, k = e & 127;
    float v = sel ? Wg2[k * 128 + n] : Wg1[k * 128 + n];
    if (sel) g_w2h[e] = h1(v);
    else     g_w1h[e] = h1(v);
}

// ---------------- batched SpMM over all TT timesteps ----------------
// warp wg in [0, TT*NN): t = wg/NN, n = wg%NN.
// input addr = n*ldp + t*tstride + lane*2 (u32 pairs); output row t*NN+n of g_mb.
__global__ __launch_bounds__(256) void spmm_batched(const u32* __restrict__ X,
                                                    int ldp, int tstride) {
    int wg = (blockIdx.x * blockDim.x + threadIdx.x) >> 5;
    int lane = threadIdx.x & 31;
    if (wg >= TT * NN) return;
    int t = wg / NN;
    int n_ = wg - t * NN;
    const u32* Xr = X + (size_t)n_ * 0;  // silence unused warn pattern
    int s0 = g_rowptr[n_], s1 = g_rowptr[n_ + 1];
    float4 acc = make_float4(0.f, 0.f, 0.f, 0.f);
    const size_t toff = (size_t)t * tstride + lane * 2;
    for (int base = s0; base < s1; base += 32) {
        int n = min(32, s1 - base);
        int s = 0; float ns = 0.f;
        if (lane < n) {
            s = g_srcsorted[base + lane];
            ns = g_norm_src[s];
        }
        for (int j = 0; j < n; j++) {
            int   sj = __shfl_sync(0xffffffffu, s, j);
            float nj = __shfl_sync(0xffffffffu, ns, j);
            uint2 v = *(const uint2*)(X + (size_t)sj * ldp + toff);
            float2 f01 = __half22float2(*reinterpret_cast<const __half2*>(&v.x));
            float2 f23 = __half22float2(*reinterpret_cast<const __half2*>(&v.y));
            acc.x += f01.x * nj; acc.y += f01.y * nj;
            acc.z += f23.x * nj; acc.w += f23.y * nj;
        }
    }
    (void)Xr;
    float nd = g_norm_dst[n_];
    size_t q = (((size_t)t * NN + n_) * D + lane * 4) >> 2;
    ((uint2*)g_mb)[q] = make_uint2((u32)h1(acc.x * nd) | ((u32)h1(acc.y * nd) << 16),
                                   (u32)h1(acc.z * nd) | ((u32)h1(acc.w * nd) << 16));
}

// ==================================================================================
// fp16 GEMM, mma.m16n8k16, BM=128 BN=128 BK=16.
// 3-stage cp.async pipeline, ONE __syncthreads per chunk, ldmatrix, term-major mma.
// MODE 0: batched graph conv, grid.x = GX*TT: t = bx/GX, local tile lt = bx%GX.
//         rows [t*NN + lt*128 ...), valid local rows < NN. Ch store fp16 (opt),
//         hs colsum into hsacc[t*D ...] (opt). K=128.
// MODE 1: LSTM, K=256 (A = [x_t | h]): fused cell epilogue. grid.y = 4.
// ==================================================================================
template <int MODE>
__global__ __launch_bounds__(256, 2) void gemm_f16(
    const u32* __restrict__ A0, int ldap,      // pairs/row
    const u32* __restrict__ A1,                // MODE1 h (ld 64)
    const u32* __restrict__ Bh, int ldbp,
    const float* __restrict__ bias,
    u16* __restrict__ Ch, float* __restrict__ hsacc,
    u16* __restrict__ ho_, float* __restrict__ hta)
{
    __shared__ __align__(16) u32 sh[8192];   // 3 x 8KB staging; epilogue reuses 32KB
    float* gtile = (float*)sh;               // epilogue [64][128]

    const int tid = threadIdx.x, lane = tid & 31;
    const int warpId = tid >> 5;
    const int warpM = warpId >> 2, warpN = warpId & 3;

    int tIdx = 0, ltile = blockIdx.x;
    if (MODE == 0) { tIdx = blockIdx.x / GX; ltile = blockIdx.x - tIdx * GX; }
    const int rowLoc = ltile * 128;                       // local row base (within one t)
    const size_t rowGlb = (MODE == 0) ? ((size_t)tIdx * NN + rowLoc) : (size_t)rowLoc;
    const int colBase = blockIdx.y * 128;

    const u32 smb = smem_u32(sh);

    float acc[4][4][4];
#pragma unroll
    for (int a = 0; a < 4; a++)
#pragma unroll
        for (int b = 0; b < 4; b++)
#pragma unroll
            for (int c = 0; c < 4; c++) acc[a][b][c] = 0.f;

    const int NCH = MODE ? 16 : 8;
    const int r_ = tid >> 1, half_ = tid & 1;        // staging coords
    const u32 stA = swz(r_, half_);                  // store offsets (constant over chunks)
    const int rowOK = (rowLoc + r_ < NN) ? 16 : 0;
    const size_t rowC = (rowLoc + r_ < NN) ? (rowGlb + r_) : rowGlb;  // clamped
    const int gcB = (MODE ? colBase : 0) + r_;

    // stage buffer: A[0,4096) B[4096,8192); stride 8192; 3 stages
    auto issue_chunk = [&](int ch) {
        u32 bufoff = (u32)((ch % 3) * 8192);
        const u32* a_;
        int po, ld;
        if (MODE == 1 && ch >= 8) { a_ = A1; po = (ch - 8) * 8 + half_ * 4; ld = 64; }
        else                      { a_ = A0; po = ch * 8 + half_ * 4; ld = ldap; }
        CP_ASYNC16(smb + bufoff + stA,        a_ + rowC * ld + po, rowOK);
        int pb = ch * 8 + half_ * 4;
        CP_ASYNC16(smb + bufoff + 4096 + stA, Bh + (size_t)gcB * ldbp + pb, 16);
    };

    issue_chunk(0); CP_COMMIT();
    issue_chunk(1); CP_COMMIT();

    for (int ch = 0; ch < NCH; ch++) {
        if (ch + 1 < NCH) asm volatile("cp.async.wait_group 1;");
        else              asm volatile("cp.async.wait_group 0;");
        __syncthreads();
        const u32 bufoff = (u32)((ch % 3) * 8192);
        const u32 smA = smb + bufoff;
        const u32 smB = smb + bufoff + 4096;
        uint4 ah[4];
        uint2 bb[4];
        {
            int ra = lane & 15, ha = lane >> 4;
#pragma unroll
            for (int mi = 0; mi < 4; mi++) {
                int row = warpM * 64 + mi * 16 + ra;
                LDSM_X4(ah[mi], smA + swz(row, ha));
            }
            int rb = lane & 7, hb = (lane >> 3) & 1;
#pragma unroll
            for (int ni = 0; ni < 4; ni++) {
                int n = warpN * 32 + ni * 8 + rb;
                LDSM_X2(bb[ni], smB + swz(n, hb));
            }
        }
#pragma unroll
        for (int ni = 0; ni < 4; ni++)
#pragma unroll
            for (int mi = 0; mi < 4; mi++)
                mma16(acc[mi][ni], ah[mi], bb[ni].x, bb[ni].y);
        if (ch + 2 < NCH) { issue_chunk(ch + 2); CP_COMMIT(); }
    }

    // ---- epilogue: stage through shared, 2 row-halves of 64 ----
    float csum[4] = {0.f, 0.f, 0.f, 0.f};
    const int cq = tid & 31;

    for (int half = 0; half < 2; half++) {
        __syncthreads();
        if (warpM == half) {
#pragma unroll
            for (int mi = 0; mi < 4; mi++) {
#pragma unroll
                for (int ni = 0; ni < 4; ni++) {
                    int rloc = mi * 16 + (lane >> 2);
                    int cloc = warpN * 32 + ni * 8 + (lane & 3) * 2;
                    float b0v = bias[colBase + cloc];
                    float b1v = bias[colBase + cloc + 1];
                    gtile[rloc * 128 + cloc]           = acc[mi][ni][0] + b0v;
                    gtile[rloc * 128 + cloc + 1]       = acc[mi][ni][1] + b1v;
                    gtile[(rloc + 8) * 128 + cloc]     = acc[mi][ni][2] + b0v;
                    gtile[(rloc + 8) * 128 + cloc + 1] = acc[mi][ni][3] + b1v;
                }
            }
        }
        __syncthreads();
#pragma unroll
        for (int i = 0; i < 8; i++) {
            int e = tid + i * 256;
            int rloc = e >> 5;
            int lrow = rowLoc + half * 64 + rloc;   // local row within t (MODE0) / global (MODE1)
            if (MODE == 0) {
                float4 gv = *(const float4*)&gtile[rloc * 128 + cq * 4];
                float4 ov;
                ov.x = gelu_exact(gv.x);
                ov.y = gelu_exact(gv.y);
                ov.z = gelu_exact(gv.z);
                ov.w = gelu_exact(gv.w);
                if (lrow < NN) {
                    if (Ch != nullptr) {
                        size_t grow = (size_t)tIdx * NN + lrow;
                        uint2 pk;
                        pk.x = (u32)h1(ov.x) | ((u32)h1(ov.y) << 16);
                        pk.y = (u32)h1(ov.z) | ((u32)h1(ov.w) << 16);
                        *(uint2*)(Ch + grow * D + cq * 4) = pk;
                    }
                    csum[0] += ov.x; csum[1] += ov.y; csum[2] += ov.z; csum[3] += ov.w;
                }
            } else {
                if (lrow < NN) {
                    float4 gv = *(const float4*)&gtile[rloc * 128 + cq * 4];
                    int fg = blockIdx.y * 32 + cq;
                    size_t idx = (size_t)lrow * D + fg;
                    float cp = g_c[idx];
                    float cn = sigmoidf_(gv.y) * cp + sigmoidf_(gv.x) * tanhf(gv.z);
                    float ho = sigmoidf_(gv.w) * tanhf(cn);
                    g_c[idx] = cn;
                    hta[idx] += ho;
                    ho_[idx] = h1(ho);
                }
            }
        }
    }
    if (MODE == 0 && hsacc != nullptr) {
#pragma unroll
        for (int j = 0; j < 4; j++)
            atomicAdd(&hsacc[tIdx * D + cq * 4 + j], csum[j]);
    }
}

__global__ void finalize_kernel(float* __restrict__ out) {
    int idx = blockIdx.x * blockDim.x + threadIdx.x;
    if (idx < TT * D) out[idx] = g_hs[idx] * (1.0f / (float)NN);
    if (idx < NN * D) out[TT * D + idx] *= (1.0f / (float)TT);
}

// ---------------- launch ----------------
extern "C" void kernel_launch(void* const* d_in, const int* in_sizes, int n_in,
                              void* d_out, int out_size) {
    const float* h    = (const float*)d_in[0];
    const int*   src  = (const int*)d_in[1];
    const int*   dst  = (const int*)d_in[2];
    const float* Wg1  = (const float*)d_in[3];
    const float* bg1  = (const float*)d_in[4];
    const float* Wg2  = (const float*)d_in[5];
    const float* bg2  = (const float*)d_in[6];
    const float* w_ih = (const float*)d_in[7];
    const float* w_hh = (const float*)d_in[8];
    const float* b_ih = (const float*)d_in[9];
    const float* b_hh = (const float*)d_in[10];

    float* out    = (float*)d_out;
    float* out_ht = out + TT * D;

    u16 *pxh, *pmb, *px1b, *ph0, *ph1, *pwlh, *pw1h, *pw2h;
    float *pbp, *phs;
    cudaGetSymbolAddress((void**)&pxh, g_xh);
    cudaGetSymbolAddress((void**)&pmb, g_mb);
    cudaGetSymbolAddress((void**)&px1b, g_x1b);
    cudaGetSymbolAddress((void**)&ph0, g_h0);
    cudaGetSymbolAddress((void**)&ph1, g_h1);
    cudaGetSymbolAddress((void**)&pwlh, g_wlh);
    cudaGetSymbolAddress((void**)&pw1h, g_w1h);
    cudaGetSymbolAddress((void**)&pw2h, g_w2h);
    cudaGetSymbolAddress((void**)&pbp, g_biasp);
    cudaGetSymbolAddress((void**)&phs, g_hs);

    // fork/join resources (host objects only)
    cudaStream_t s2;
    cudaStreamCreateWithFlags(&s2, cudaStreamNonBlocking);
    cudaEvent_t e1, e2;
    cudaEventCreateWithFlags(&e1, cudaEventDisableTiming);
    cudaEventCreateWithFlags(&e2, cudaEventDisableTiming);

    // common setup on main stream
    init_kernel<<<(NN * D + 255) / 256, 256>>>(out_ht);
    wlprep_kernel<<<(512 * 256 + 255) / 256, 256>>>(w_ih, w_hh, b_ih, b_hh);
    convh_kernel<<<(int)(((size_t)NN * TT * D / 4 + 255) / 256), 256>>>(h);

    // fork: LSTM chain on s2
    cudaEventRecord(e1, 0);
    cudaStreamWaitEvent(s2, e1, 0);

    u16 *hin = ph0, *hout = ph1;
    for (int t = 0; t < TT; t++) {
        gemm_f16<1><<<dim3(GX, 4), 256, 0, s2>>>(
            (u32*)pxh + (size_t)t * 64, TT * 64,
            (u32*)hin,
            (u32*)pwlh, 128, pbp,
            nullptr, nullptr, hout, out_ht);
        u16* tmp = hin; hin = hout; hout = tmp;
    }
    cudaEventRecord(e2, s2);

    // graph chain on main stream (batched across all 12 timesteps)
    hist_kernel<<<(EE + 255) / 256, 256>>>(src, dst);
    norm_kernel<<<(NN + 255) / 256, 256>>>();
    wgprep_kernel<<<(2 * 128 * 128 + 255) / 256, 256>>>(Wg1, Wg2);
    scan_kernel<<<1, 1024>>>();
    scatter_kernel<<<(EE + 255) / 256, 256>>>(src, dst);

    const int sb = (TT * NN * 32 + 255) / 256;   // 75000 blocks
    // layer 1: spmm over x (ld TT*64 pairs, t-offset 64), gemm -> x1 batched
    spmm_batched<<<sb, 256>>>((u32*)pxh, TT * 64, 64);
    gemm_f16<0><<<dim3(GX * TT, 1), 256>>>((u32*)pmb, 64, nullptr,
                                           (u32*)pw1h, 64, bg1,
                                           px1b, nullptr, nullptr, nullptr);
    // layer 2: spmm over x1 batched (ld 64, t-offset NN*64), gemm -> hs colsum only
    spmm_batched<<<sb, 256>>>((u32*)px1b, 64, NN * 64);
    gemm_f16<0><<<dim3(GX * TT, 1), 256>>>((u32*)pmb, 64, nullptr,
                                           (u32*)pw2h, 64, bg2,
                                           nullptr, phs, nullptr, nullptr);

    // join and finalize
    cudaStreamWaitEvent(0, e2, 0);
    finalize_kernel<<<(NN * D + 255) / 256, 256>>>(out);
}